// round 1
// baseline (speedup 1.0000x reference)
#include <cuda_runtime.h>

#define CIN 128
#define KNN 16
#define NMAX 8192
#define SPLITS 8
#define EPS 1e-5f
#define SLOPE 0.01f

// ---------------- scratch (static device memory; no allocations) ----------------
__device__ __align__(16) float g_xyz4[NMAX * 4];          // packed xyz_i (x,y,z,0)
__device__ int   g_idx[NMAX * KNN];                        // final knn indices
__device__ float g_pd[NMAX * SPLITS * KNN];                // partial top-16 dists
__device__ int   g_pi[NMAX * SPLITS * KNN];                // partial top-16 idx
__device__ __align__(16) float g_Q[NMAX * CIN];
__device__ __align__(16) float g_K[NMAX * CIN];
__device__ __align__(16) float g_V[NMAX * CIN];
__device__ __align__(16) float g_w2[(size_t)NMAX * KNN * CIN];  // post-linear tensor
__device__ float g_stat[4 * CIN];   // [0:128)=sum1 [128:256)=sq1 [256:384)=sum2 [384:512)=sq2
__device__ float g_aff[4 * CIN];    // [0:128)=sc1  [128:256)=sh1 [256:384)=sc2  [384:512)=sh2

// ---------------- k0: pack xyz_i into float4, zero stat accumulators ----------------
__global__ void k_pack(const float* __restrict__ xyz_i, int N) {
    int i = blockIdx.x * 256 + threadIdx.x;
    if (i < N) {
        g_xyz4[i * 4 + 0] = xyz_i[i * 3 + 0];
        g_xyz4[i * 4 + 1] = xyz_i[i * 3 + 1];
        g_xyz4[i * 4 + 2] = xyz_i[i * 3 + 2];
        g_xyz4[i * 4 + 3] = 0.f;
    }
    if (i < 4 * CIN) g_stat[i] = 0.f;
}

// ---------------- k1: knn partial top-16 per (query, split) ----------------
__global__ void k_knn(const float* __restrict__ xyz_last, int N) {
    int q = blockIdx.x * 256 + threadIdx.x;
    int split = blockIdx.y;
    int per = N / SPLITS;
    int c0 = split * per;

    float qx = xyz_last[q * 3 + 0];
    float qy = xyz_last[q * 3 + 1];
    float qz = xyz_last[q * 3 + 2];

    float bd[KNN];
    int   bi[KNN];
#pragma unroll
    for (int s = 0; s < KNN; s++) { bd[s] = 1e30f; bi[s] = -1; }

    const float4* X = (const float4*)g_xyz4;
#pragma unroll 4
    for (int j = 0; j < per; j++) {
        float4 c = X[c0 + j];
        float dx = qx - c.x, dy = qy - c.y, dz = qz - c.z;
        float d2 = dx * dx + dy * dy + dz * dz;
        if (d2 < bd[KNN - 1]) {
            bd[KNN - 1] = d2; bi[KNN - 1] = c0 + j;
#pragma unroll
            for (int s = KNN - 1; s > 0; --s) {
                if (bd[s] < bd[s - 1]) {
                    float td = bd[s]; bd[s] = bd[s - 1]; bd[s - 1] = td;
                    int ti = bi[s]; bi[s] = bi[s - 1]; bi[s - 1] = ti;
                }
            }
        }
    }
    int base = (q * SPLITS + split) * KNN;
#pragma unroll
    for (int s = 0; s < KNN; s++) { g_pd[base + s] = bd[s]; g_pi[base + s] = bi[s]; }
}

// ---------------- k1b: merge SPLITS sorted lists of 16 -> final 16 ----------------
__global__ void k_merge(int N) {
    int q = blockIdx.x * 256 + threadIdx.x;
    if (q >= N) return;
    int base = q * SPLITS * KNN;
    float h[SPLITS];
    int   p[SPLITS];
#pragma unroll
    for (int s = 0; s < SPLITS; s++) { p[s] = 0; h[s] = g_pd[base + s * KNN]; }
#pragma unroll
    for (int r = 0; r < KNN; r++) {
        float best = h[0]; int bs = 0;
#pragma unroll
        for (int s = 1; s < SPLITS; s++)
            if (h[s] < best) { best = h[s]; bs = s; }
        int wi = 0;
#pragma unroll
        for (int s = 0; s < SPLITS; s++) {
            if (s == bs) {
                wi = g_pi[base + s * KNN + p[s]];
                p[s]++;
                h[s] = (p[s] < KNN) ? g_pd[base + s * KNN + p[s]] : 1e30f;
            }
        }
        g_idx[q * KNN + r] = wi;
    }
}

// ---------------- k2: Q/K/V projections (no biases: bq/bk cancel in BN; bv added later)
// C[M x 128] = A[M x 128] @ W[128 x 128]^T, BM=128, BK=32, 256 threads, 8x8 per thread
__global__ void k_gemm_qkv(const float* __restrict__ fea_i,
                           const float* __restrict__ fea_last,
                           const float* __restrict__ Wq,
                           const float* __restrict__ Wk,
                           const float* __restrict__ Wv) {
    int which = blockIdx.y;
    const float* A = (which == 0) ? fea_last : fea_i;
    const float* W = (which == 0) ? Wq : (which == 1 ? Wk : Wv);
    float* C = (which == 0) ? g_Q : (which == 1 ? g_K : g_V);

    __shared__ float As[32][132];
    __shared__ float Ws[32][132];

    int t = threadIdx.x;          // 256
    int tr = t & 15, tc = t >> 4; // 16 x 16 grid of threads
    int row0 = blockIdx.x * 128;
    int lr = t >> 1;              // load row 0..127
    int lc = (t & 1) * 16;        // 0 or 16

    float acc[8][8];
#pragma unroll
    for (int i = 0; i < 8; i++)
#pragma unroll
        for (int j = 0; j < 8; j++) acc[i][j] = 0.f;

    for (int ch = 0; ch < 128; ch += 32) {
        const float4* Ar = (const float4*)(A + (size_t)(row0 + lr) * 128 + ch + lc);
        const float4* Wr = (const float4*)(W + (size_t)lr * 128 + ch + lc);
#pragma unroll
        for (int v = 0; v < 4; v++) {
            float4 a = Ar[v];
            As[lc + v * 4 + 0][lr] = a.x; As[lc + v * 4 + 1][lr] = a.y;
            As[lc + v * 4 + 2][lr] = a.z; As[lc + v * 4 + 3][lr] = a.w;
            float4 w = Wr[v];
            Ws[lc + v * 4 + 0][lr] = w.x; Ws[lc + v * 4 + 1][lr] = w.y;
            Ws[lc + v * 4 + 2][lr] = w.z; Ws[lc + v * 4 + 3][lr] = w.w;
        }
        __syncthreads();
#pragma unroll
        for (int kk = 0; kk < 32; kk++) {
            float4 a0 = *(const float4*)&As[kk][tr * 8];
            float4 a1 = *(const float4*)&As[kk][tr * 8 + 4];
            float4 b0 = *(const float4*)&Ws[kk][tc * 8];
            float4 b1 = *(const float4*)&Ws[kk][tc * 8 + 4];
            float a[8] = {a0.x, a0.y, a0.z, a0.w, a1.x, a1.y, a1.z, a1.w};
            float b[8] = {b0.x, b0.y, b0.z, b0.w, b1.x, b1.y, b1.z, b1.w};
#pragma unroll
            for (int i = 0; i < 8; i++)
#pragma unroll
                for (int j = 0; j < 8; j++) acc[i][j] = fmaf(a[i], b[j], acc[i][j]);
        }
        __syncthreads();
    }
#pragma unroll
    for (int i = 0; i < 8; i++) {
        float* cr = C + (size_t)(row0 + tr * 8 + i) * 128 + tc * 8;
        ((float4*)cr)[0] = make_float4(acc[i][0], acc[i][1], acc[i][2], acc[i][3]);
        ((float4*)cr)[1] = make_float4(acc[i][4], acc[i][5], acc[i][6], acc[i][7]);
    }
}

// ---------------- k3: BN1 statistics over w1 = Q[n] - K[idx[n,k]] ----------------
__global__ void k_stats1(int N) {
    int t = threadIdx.x;           // 256
    int c = t & 127, g = t >> 7;   // channel, half
    int r0 = blockIdx.x * 512;
    float s = 0.f, q = 0.f;
    for (int r = r0 + g; r < r0 + 512; r += 2) {
        int n = r >> 4;
        int j = g_idx[r];
        float w = g_Q[(size_t)n * 128 + c] - g_K[(size_t)j * 128 + c];
        s += w;
        q = fmaf(w, w, q);
    }
    __shared__ float sh[256];
    sh[t] = s; __syncthreads();
    if (g == 0) atomicAdd(&g_stat[c], sh[c] + sh[128 + c]);
    __syncthreads();
    sh[t] = q; __syncthreads();
    if (g == 0) atomicAdd(&g_stat[128 + c], sh[c] + sh[128 + c]);
}

// ---------------- finalize BN stats -> affine scale/shift ----------------
__global__ void k_finalize(const float* __restrict__ gamma, const float* __restrict__ beta,
                           int soff, int aoff, float inv_cnt) {
    int c = threadIdx.x;  // 128
    float mean = g_stat[soff + c] * inv_cnt;
    float var  = g_stat[soff + 128 + c] * inv_cnt - mean * mean;
    float sc = gamma[c] * rsqrtf(var + EPS);
    g_aff[aoff + c] = sc;
    g_aff[aoff + 128 + c] = beta[c] - mean * sc;
}

// ---------------- k5: w2 = leaky(aff1(Q - K[idx])) @ Wl^T, + BN2 stat accumulation
// rows = n*16+k (NK total), BM=128, BK=32, 256 threads, 8x8 per thread
__global__ void k_gemm_w(const float* __restrict__ Wl) {
    __shared__ float As[32][132];
    __shared__ float Ws[32][132];
    __shared__ float s_sc[128], s_sh[128];
    __shared__ float ssum[128], ssq[128];

    int t = threadIdx.x;
    int tr = t & 15, tc = t >> 4;
    int row0 = blockIdx.x * 128;
    int lr = t >> 1;
    int lc = (t & 1) * 16;

    if (t < 128) { s_sc[t] = g_aff[t]; s_sh[t] = g_aff[128 + t]; ssum[t] = 0.f; ssq[t] = 0.f; }
    __syncthreads();

    int nk = row0 + lr;
    int n = nk >> 4;
    int jrow = g_idx[nk];
    const float4* Qr = (const float4*)(g_Q + (size_t)n * 128);
    const float4* Kr = (const float4*)(g_K + (size_t)jrow * 128);

    float acc[8][8];
#pragma unroll
    for (int i = 0; i < 8; i++)
#pragma unroll
        for (int j = 0; j < 8; j++) acc[i][j] = 0.f;

    for (int ch = 0; ch < 128; ch += 32) {
        const float4* Wr = (const float4*)(Wl + (size_t)lr * 128 + ch + lc);
        int cb = (ch + lc) >> 2;  // float4 index
#pragma unroll
        for (int v = 0; v < 4; v++) {
            float4 a = Qr[cb + v];
            float4 b = Kr[cb + v];
            int c0 = ch + lc + v * 4;
            float x0 = fmaf(a.x - b.x, s_sc[c0 + 0], s_sh[c0 + 0]); x0 = x0 >= 0.f ? x0 : SLOPE * x0;
            float x1 = fmaf(a.y - b.y, s_sc[c0 + 1], s_sh[c0 + 1]); x1 = x1 >= 0.f ? x1 : SLOPE * x1;
            float x2 = fmaf(a.z - b.z, s_sc[c0 + 2], s_sh[c0 + 2]); x2 = x2 >= 0.f ? x2 : SLOPE * x2;
            float x3 = fmaf(a.w - b.w, s_sc[c0 + 3], s_sh[c0 + 3]); x3 = x3 >= 0.f ? x3 : SLOPE * x3;
            As[lc + v * 4 + 0][lr] = x0; As[lc + v * 4 + 1][lr] = x1;
            As[lc + v * 4 + 2][lr] = x2; As[lc + v * 4 + 3][lr] = x3;
            float4 w = Wr[v];
            Ws[lc + v * 4 + 0][lr] = w.x; Ws[lc + v * 4 + 1][lr] = w.y;
            Ws[lc + v * 4 + 2][lr] = w.z; Ws[lc + v * 4 + 3][lr] = w.w;
        }
        __syncthreads();
#pragma unroll
        for (int kk = 0; kk < 32; kk++) {
            float4 a0 = *(const float4*)&As[kk][tr * 8];
            float4 a1 = *(const float4*)&As[kk][tr * 8 + 4];
            float4 b0 = *(const float4*)&Ws[kk][tc * 8];
            float4 b1 = *(const float4*)&Ws[kk][tc * 8 + 4];
            float a[8] = {a0.x, a0.y, a0.z, a0.w, a1.x, a1.y, a1.z, a1.w};
            float b[8] = {b0.x, b0.y, b0.z, b0.w, b1.x, b1.y, b1.z, b1.w};
#pragma unroll
            for (int i = 0; i < 8; i++)
#pragma unroll
                for (int j = 0; j < 8; j++) acc[i][j] = fmaf(a[i], b[j], acc[i][j]);
        }
        __syncthreads();
    }

    // per-column partial sums for BN2 (bl excluded: cancels in BN)
#pragma unroll
    for (int j = 0; j < 8; j++) {
        float cs = 0.f, cq = 0.f;
#pragma unroll
        for (int i = 0; i < 8; i++) { float v = acc[i][j]; cs += v; cq = fmaf(v, v, cq); }
        atomicAdd(&ssum[tc * 8 + j], cs);
        atomicAdd(&ssq[tc * 8 + j], cq);
    }
    // store w2
#pragma unroll
    for (int i = 0; i < 8; i++) {
        float* cr = g_w2 + (size_t)(row0 + tr * 8 + i) * 128 + tc * 8;
        ((float4*)cr)[0] = make_float4(acc[i][0], acc[i][1], acc[i][2], acc[i][3]);
        ((float4*)cr)[1] = make_float4(acc[i][4], acc[i][5], acc[i][6], acc[i][7]);
    }
    __syncthreads();
    if (t < 128) {
        atomicAdd(&g_stat[256 + t], ssum[t]);
        atomicAdd(&g_stat[384 + t], ssq[t]);
    }
}

// ---------------- k7: aff2 + leaky + softmax over K + weighted V sum ----------------
__global__ void k_out(const float* __restrict__ bv, float* __restrict__ out, int N) {
    int n = blockIdx.x;
    int c = threadIdx.x;  // 128
    __shared__ int sidx[KNN];
    if (c < KNN) sidx[c] = g_idx[n * KNN + c];
    __syncthreads();

    float sc2 = g_aff[256 + c], sh2 = g_aff[384 + c];
    float tv[KNN];
    float m = -1e30f;
#pragma unroll
    for (int k = 0; k < KNN; k++) {
        float x = g_w2[(size_t)(n * KNN + k) * 128 + c];
        x = fmaf(x, sc2, sh2);
        x = x >= 0.f ? x : SLOPE * x;
        tv[k] = x;
        m = fmaxf(m, x);
    }
    float s = 0.f;
#pragma unroll
    for (int k = 0; k < KNN; k++) { float e = __expf(tv[k] - m); tv[k] = e; s += e; }
    float inv = 1.f / s;
    float b = bv[c];
    float acc = 0.f;
#pragma unroll
    for (int k = 0; k < KNN; k++) {
        float v = g_V[(size_t)sidx[k] * 128 + c] + b;
        acc = fmaf(tv[k] * inv, v, acc);
    }
    out[(size_t)n * 128 + c] = acc;
}

// ---------------- launch ----------------
extern "C" void kernel_launch(void* const* d_in, const int* in_sizes, int n_in,
                              void* d_out, int out_size) {
    const float* fea_i    = (const float*)d_in[0];
    const float* fea_last = (const float*)d_in[1];
    const float* xyz_i    = (const float*)d_in[2];
    const float* xyz_last = (const float*)d_in[3];
    // d_in[4] = batch (unused, single batch)
    const float* Wq = (const float*)d_in[5];
    // d_in[6] bq cancels in BN
    const float* Wk = (const float*)d_in[7];
    // d_in[8] bk cancels in BN
    const float* Wv = (const float*)d_in[9];
    const float* bv = (const float*)d_in[10];
    const float* g1 = (const float*)d_in[11];
    const float* b1 = (const float*)d_in[12];
    const float* Wl = (const float*)d_in[13];
    // d_in[14] bl cancels in BN
    const float* g2 = (const float*)d_in[15];
    const float* b2 = (const float*)d_in[16];

    int N = in_sizes[0] / CIN;
    int NK = N * KNN;

    k_pack<<<(N + 255) / 256, 256>>>(xyz_i, N);

    dim3 gk(N / 256, SPLITS);
    k_knn<<<gk, 256>>>(xyz_last, N);
    k_merge<<<(N + 255) / 256, 256>>>(N);

    dim3 gq(N / 128, 3);
    k_gemm_qkv<<<gq, 256>>>(fea_i, fea_last, Wq, Wk, Wv);

    k_stats1<<<NK / 512, 256>>>(N);
    k_finalize<<<1, 128>>>(g1, b1, 0, 0, 1.0f / (float)NK);

    k_gemm_w<<<NK / 128, 256>>>(Wl);
    k_finalize<<<1, 128>>>(g2, b2, 256, 256, 1.0f / (float)NK);

    k_out<<<N, 128>>>(bv, (float*)d_out, N);
}

// round 3
// speedup vs baseline: 1.0159x; 1.0159x over previous
#include <cuda_runtime.h>
#include <cuda_bf16.h>
#include <cstdint>

#define CIN 128
#define KNN 16
#define NMAX 8192
#define SPLITS 8
#define EPS 1e-5f
#define SLOPE 0.01f
#define PAD 136   // bf16 elements per smem row (stride); banks = 4*g + c -> conflict-free

// ---------------- scratch (static device memory; no allocations) ----------------
__device__ __align__(16) float g_xyz4[NMAX * 4];
__device__ int   g_idx[NMAX * KNN];
__device__ float g_pd[NMAX * SPLITS * KNN];
__device__ int   g_pi[NMAX * SPLITS * KNN];
__device__ __align__(16) float g_Q[NMAX * CIN];
__device__ __align__(16) float g_K[NMAX * CIN];
__device__ __align__(16) float g_V[NMAX * CIN];
__device__ __align__(16) float g_w2[(size_t)NMAX * KNN * CIN];
__device__ float g_stat[4 * CIN];   // [0:128)=sum1 [128:256)=sq1 [256:384)=sum2 [384:512)=sq2
__device__ float g_aff[4 * CIN];    // [0:128)=sc1  [128:256)=sh1 [256:384)=sc2  [384:512)=sh2

// fp32 -> (bf16 hi, bf16 lo) pair pack
__device__ __forceinline__ void split_pair(float x0, float x1, uint32_t& hp, uint32_t& lp) {
    __nv_bfloat16 h0 = __float2bfloat16(x0);
    __nv_bfloat16 h1 = __float2bfloat16(x1);
    __nv_bfloat16 l0 = __float2bfloat16(x0 - __bfloat162float(h0));
    __nv_bfloat16 l1 = __float2bfloat16(x1 - __bfloat162float(h1));
    hp = ((uint32_t)__bfloat16_as_ushort(h1) << 16) | __bfloat16_as_ushort(h0);
    lp = ((uint32_t)__bfloat16_as_ushort(l1) << 16) | __bfloat16_as_ushort(l0);
}

__device__ __forceinline__ void store_split4(char* hi, char* lo, int r, int c, float4 a) {
    uint32_t h0, l0, h1, l1;
    split_pair(a.x, a.y, h0, l0);
    split_pair(a.z, a.w, h1, l1);
    int off = (r * PAD + c) * 2;
    *(uint32_t*)(hi + off)     = h0;
    *(uint32_t*)(lo + off)     = l0;
    *(uint32_t*)(hi + off + 4) = h1;
    *(uint32_t*)(lo + off + 4) = l1;
}

__device__ __forceinline__ void mma16816(float* d, const uint32_t* a, const uint32_t* b) {
    asm volatile(
        "mma.sync.aligned.m16n8k16.row.col.f32.bf16.bf16.f32 "
        "{%0,%1,%2,%3}, {%4,%5,%6,%7}, {%8,%9}, {%0,%1,%2,%3};"
        : "+f"(d[0]), "+f"(d[1]), "+f"(d[2]), "+f"(d[3])
        : "r"(a[0]), "r"(a[1]), "r"(a[2]), "r"(a[3]), "r"(b[0]), "r"(b[1]));
}

// ---------------- k0: pack xyz_i into float4, zero stat accumulators ----------------
__global__ void k_pack(const float* __restrict__ xyz_i, int N) {
    int i = blockIdx.x * 256 + threadIdx.x;
    if (i < N) {
        g_xyz4[i * 4 + 0] = xyz_i[i * 3 + 0];
        g_xyz4[i * 4 + 1] = xyz_i[i * 3 + 1];
        g_xyz4[i * 4 + 2] = xyz_i[i * 3 + 2];
        g_xyz4[i * 4 + 3] = 0.f;
    }
    if (i < 4 * CIN) g_stat[i] = 0.f;
}

// ---------------- k1: knn partial top-16 per (query, split) ----------------
__global__ void k_knn(const float* __restrict__ xyz_last, int N) {
    int q = blockIdx.x * 256 + threadIdx.x;
    int split = blockIdx.y;
    int per = N / SPLITS;
    int c0 = split * per;

    float qx = xyz_last[q * 3 + 0];
    float qy = xyz_last[q * 3 + 1];
    float qz = xyz_last[q * 3 + 2];

    float bd[KNN];
    int   bi[KNN];
#pragma unroll
    for (int s = 0; s < KNN; s++) { bd[s] = 1e30f; bi[s] = -1; }

    const float4* X = (const float4*)g_xyz4;
#pragma unroll 4
    for (int j = 0; j < per; j++) {
        float4 c = X[c0 + j];
        float dx = qx - c.x, dy = qy - c.y, dz = qz - c.z;
        float d2 = dx * dx + dy * dy + dz * dz;
        if (d2 < bd[KNN - 1]) {
            bd[KNN - 1] = d2; bi[KNN - 1] = c0 + j;
#pragma unroll
            for (int s = KNN - 1; s > 0; --s) {
                if (bd[s] < bd[s - 1]) {
                    float td = bd[s]; bd[s] = bd[s - 1]; bd[s - 1] = td;
                    int ti = bi[s]; bi[s] = bi[s - 1]; bi[s - 1] = ti;
                }
            }
        }
    }
    int base = (q * SPLITS + split) * KNN;
#pragma unroll
    for (int s = 0; s < KNN; s++) { g_pd[base + s] = bd[s]; g_pi[base + s] = bi[s]; }
}

// ---------------- k1b: merge SPLITS sorted lists of 16 -> final 16 ----------------
__global__ void k_merge(int N) {
    int q = blockIdx.x * 256 + threadIdx.x;
    if (q >= N) return;
    int base = q * SPLITS * KNN;
    float h[SPLITS];
    int   p[SPLITS];
#pragma unroll
    for (int s = 0; s < SPLITS; s++) { p[s] = 0; h[s] = g_pd[base + s * KNN]; }
#pragma unroll
    for (int r = 0; r < KNN; r++) {
        float best = h[0]; int bs = 0;
#pragma unroll
        for (int s = 1; s < SPLITS; s++)
            if (h[s] < best) { best = h[s]; bs = s; }
        int wi = 0;
#pragma unroll
        for (int s = 0; s < SPLITS; s++) {
            if (s == bs) {
                wi = g_pi[base + s * KNN + p[s]];
                p[s]++;
                h[s] = (p[s] < KNN) ? g_pd[base + s * KNN + p[s]] : 1e30f;
            }
        }
        g_idx[q * KNN + r] = wi;
    }
}

// ---------------- mma.sync GEMM: D[128x128] = A[128x128] @ B[128x128]^T ----------------
// mode 0: A rows from fea (blockIdx.y selects Q/K/V), C -> g_Q/g_K/g_V
// mode 1: A row nk = leaky(aff1(Q[n] - K[idx[nk]])), C -> g_w2, fused BN2 stats
// bf16 3-term split: Ah*Bh + Al*Bh + Ah*Bl
#define SM_AHI 0
#define SM_ALO (128 * PAD * 2)
#define SM_BHI (2 * 128 * PAD * 2)
#define SM_BLO (3 * 128 * PAD * 2)
#define SM_AFF (4 * 128 * PAD * 2)        // 256 floats
#define SM_SUM (SM_AFF + 1024)            // 128 floats
#define SM_SQ  (SM_SUM + 512)             // 128 floats
#define SMEM_TOTAL (SM_SQ + 512)

#define LDS32(base, r, col) (*(const uint32_t*)((base) + ((r) * PAD + (col)) * 2))

__global__ void __launch_bounds__(256) k_mma_gemm(
    int mode,
    const float* __restrict__ fea_i, const float* __restrict__ fea_last,
    const float* __restrict__ Wq, const float* __restrict__ Wk,
    const float* __restrict__ Wvl)
{
    extern __shared__ char smem[];
    int t = threadIdx.x;
    int lane = t & 31, wid = t >> 5;
    int g = lane >> 2, c4 = lane & 3;
    int wm = wid & 3, wn = wid >> 2;
    int row0 = blockIdx.x * 128;

    char* Ah = smem + SM_AHI;
    char* Al = smem + SM_ALO;
    char* Bh = smem + SM_BHI;
    char* Bl = smem + SM_BLO;
    float* s_aff = (float*)(smem + SM_AFF);
    float* s_sum = (float*)(smem + SM_SUM);
    float* s_sq  = (float*)(smem + SM_SQ);

    const float* B;
    float* C;
    const float* Asrc = nullptr;
    if (mode == 0) {
        int which = blockIdx.y;
        Asrc = (which == 0) ? fea_last : fea_i;
        B = (which == 0) ? Wq : (which == 1 ? Wk : Wvl);
        C = (which == 0) ? g_Q : (which == 1 ? g_K : g_V);
    } else {
        B = Wvl;
        C = g_w2;
    }

    if (mode == 1 && t < 128) {
        s_aff[t] = g_aff[t];
        s_aff[128 + t] = g_aff[128 + t];
        s_sum[t] = 0.f;
        s_sq[t]  = 0.f;
    }
    if (mode == 1) __syncthreads();

    // ---- prep: thread t handles row r = t>>1, cols (t&1)*64..+63
    {
        int r = t >> 1;
        int ccol = (t & 1) * 64;
        // B tile (weights)
        const float4* Br = (const float4*)(B + (size_t)r * 128 + ccol);
#pragma unroll
        for (int v = 0; v < 16; v++)
            store_split4(Bh, Bl, r, ccol + 4 * v, Br[v]);
        // A tile
        if (mode == 0) {
            const float4* Ar = (const float4*)(Asrc + (size_t)(row0 + r) * 128 + ccol);
#pragma unroll
            for (int v = 0; v < 16; v++)
                store_split4(Ah, Al, r, ccol + 4 * v, Ar[v]);
        } else {
            int nk = row0 + r;
            int n = nk >> 4;
            int j = g_idx[nk];
            const float4* Qr = (const float4*)(g_Q + (size_t)n * 128 + ccol);
            const float4* Kr = (const float4*)(g_K + (size_t)j * 128 + ccol);
#pragma unroll
            for (int v = 0; v < 16; v++) {
                float4 a = Qr[v];
                float4 b = Kr[v];
                int cc = ccol + 4 * v;
                float x0 = fmaf(a.x - b.x, s_aff[cc + 0], s_aff[128 + cc + 0]);
                float x1 = fmaf(a.y - b.y, s_aff[cc + 1], s_aff[128 + cc + 1]);
                float x2 = fmaf(a.z - b.z, s_aff[cc + 2], s_aff[128 + cc + 2]);
                float x3 = fmaf(a.w - b.w, s_aff[cc + 3], s_aff[128 + cc + 3]);
                x0 = x0 >= 0.f ? x0 : SLOPE * x0;
                x1 = x1 >= 0.f ? x1 : SLOPE * x1;
                x2 = x2 >= 0.f ? x2 : SLOPE * x2;
                x3 = x3 >= 0.f ? x3 : SLOPE * x3;
                store_split4(Ah, Al, r, cc, make_float4(x0, x1, x2, x3));
            }
        }
    }
    __syncthreads();

    // ---- mma mainloop: warp tile 32(m) x 64(n), fragments via conflict-free LDS
    float acc[2][8][4];
#pragma unroll
    for (int mf = 0; mf < 2; mf++)
#pragma unroll
        for (int nf = 0; nf < 8; nf++)
#pragma unroll
            for (int e = 0; e < 4; e++) acc[mf][nf][e] = 0.f;

#pragma unroll 1
    for (int s = 0; s < 8; s++) {
        int k0 = s * 16;
        uint32_t ah[2][4], al[2][4], bh[8][2], bl[8][2];
#pragma unroll
        for (int mf = 0; mf < 2; mf++) {
            int r = wm * 32 + mf * 16 + g;
            int kc = k0 + 2 * c4;
            ah[mf][0] = LDS32(Ah, r,     kc);
            ah[mf][1] = LDS32(Ah, r + 8, kc);
            ah[mf][2] = LDS32(Ah, r,     kc + 8);
            ah[mf][3] = LDS32(Ah, r + 8, kc + 8);
            al[mf][0] = LDS32(Al, r,     kc);
            al[mf][1] = LDS32(Al, r + 8, kc);
            al[mf][2] = LDS32(Al, r,     kc + 8);
            al[mf][3] = LDS32(Al, r + 8, kc + 8);
        }
#pragma unroll
        for (int nf = 0; nf < 8; nf++) {
            int n = wn * 64 + nf * 8 + g;
            int kc = k0 + 2 * c4;
            bh[nf][0] = LDS32(Bh, n, kc);
            bh[nf][1] = LDS32(Bh, n, kc + 8);
            bl[nf][0] = LDS32(Bl, n, kc);
            bl[nf][1] = LDS32(Bl, n, kc + 8);
        }
#pragma unroll
        for (int mf = 0; mf < 2; mf++)
#pragma unroll
            for (int nf = 0; nf < 8; nf++) {
                mma16816(acc[mf][nf], ah[mf], bh[nf]);
                mma16816(acc[mf][nf], al[mf], bh[nf]);
                mma16816(acc[mf][nf], ah[mf], bl[nf]);
            }
    }

    // ---- epilogue: write C (+ BN2 stats in mode 1)
#pragma unroll
    for (int mf = 0; mf < 2; mf++)
#pragma unroll
        for (int nf = 0; nf < 8; nf++) {
            int row = row0 + wm * 32 + mf * 16 + g;
            int col = wn * 64 + nf * 8 + 2 * c4;
            *(float2*)(C + (size_t)row * 128 + col) =
                make_float2(acc[mf][nf][0], acc[mf][nf][1]);
            *(float2*)(C + (size_t)(row + 8) * 128 + col) =
                make_float2(acc[mf][nf][2], acc[mf][nf][3]);
        }

    if (mode == 1) {
#pragma unroll
        for (int nf = 0; nf < 8; nf++) {
            int col = wn * 64 + nf * 8 + 2 * c4;
            float v00 = acc[0][nf][0], v02 = acc[0][nf][2];
            float v10 = acc[1][nf][0], v12 = acc[1][nf][2];
            float s0 = v00 + v02 + v10 + v12;
            float q0 = v00 * v00 + v02 * v02 + v10 * v10 + v12 * v12;
            atomicAdd(&s_sum[col], s0);
            atomicAdd(&s_sq[col], q0);
            float v01 = acc[0][nf][1], v03 = acc[0][nf][3];
            float v11 = acc[1][nf][1], v13 = acc[1][nf][3];
            float s1 = v01 + v03 + v11 + v13;
            float q1 = v01 * v01 + v03 * v03 + v11 * v11 + v13 * v13;
            atomicAdd(&s_sum[col + 1], s1);
            atomicAdd(&s_sq[col + 1], q1);
        }
        __syncthreads();
        if (t < 128) {
            atomicAdd(&g_stat[256 + t], s_sum[t]);
            atomicAdd(&g_stat[384 + t], s_sq[t]);
        }
    }
}

// ---------------- k3: BN1 statistics over w1 = Q[n] - K[idx[n,k]] ----------------
__global__ void k_stats1(int N) {
    int t = threadIdx.x;
    int c = t & 127, g = t >> 7;
    int r0 = blockIdx.x * 512;
    float s = 0.f, q = 0.f;
    for (int r = r0 + g; r < r0 + 512; r += 2) {
        int n = r >> 4;
        int j = g_idx[r];
        float w = g_Q[(size_t)n * 128 + c] - g_K[(size_t)j * 128 + c];
        s += w;
        q = fmaf(w, w, q);
    }
    __shared__ float sh[256];
    sh[t] = s; __syncthreads();
    if (g == 0) atomicAdd(&g_stat[c], sh[c] + sh[128 + c]);
    __syncthreads();
    sh[t] = q; __syncthreads();
    if (g == 0) atomicAdd(&g_stat[128 + c], sh[c] + sh[128 + c]);
}

// ---------------- finalize BN stats -> affine scale/shift ----------------
__global__ void k_finalize(const float* __restrict__ gamma, const float* __restrict__ beta,
                           int soff, int aoff, float inv_cnt) {
    int c = threadIdx.x;
    float mean = g_stat[soff + c] * inv_cnt;
    float var  = g_stat[soff + 128 + c] * inv_cnt - mean * mean;
    float sc = gamma[c] * rsqrtf(var + EPS);
    g_aff[aoff + c] = sc;
    g_aff[aoff + 128 + c] = beta[c] - mean * sc;
}

// ---------------- k7: aff2 + leaky + softmax over K + weighted V sum ----------------
__global__ void k_out(const float* __restrict__ bv, float* __restrict__ out, int N) {
    int n = blockIdx.x;
    int c = threadIdx.x;
    __shared__ int sidx[KNN];
    if (c < KNN) sidx[c] = g_idx[n * KNN + c];
    __syncthreads();

    float sc2 = g_aff[256 + c], sh2 = g_aff[384 + c];
    float tv[KNN];
    float m = -1e30f;
#pragma unroll
    for (int k = 0; k < KNN; k++) {
        float x = g_w2[(size_t)(n * KNN + k) * 128 + c];
        x = fmaf(x, sc2, sh2);
        x = x >= 0.f ? x : SLOPE * x;
        tv[k] = x;
        m = fmaxf(m, x);
    }
    float s = 0.f;
#pragma unroll
    for (int k = 0; k < KNN; k++) { float e = __expf(tv[k] - m); tv[k] = e; s += e; }
    float inv = 1.f / s;
    float b = bv[c];
    float acc = 0.f;
#pragma unroll
    for (int k = 0; k < KNN; k++) {
        float v = g_V[(size_t)sidx[k] * 128 + c] + b;
        acc = fmaf(tv[k] * inv, v, acc);
    }
    out[(size_t)n * 128 + c] = acc;
}

// ---------------- launch ----------------
extern "C" void kernel_launch(void* const* d_in, const int* in_sizes, int n_in,
                              void* d_out, int out_size) {
    const float* fea_i    = (const float*)d_in[0];
    const float* fea_last = (const float*)d_in[1];
    const float* xyz_i    = (const float*)d_in[2];
    const float* xyz_last = (const float*)d_in[3];
    const float* Wq = (const float*)d_in[5];
    const float* Wk = (const float*)d_in[7];
    const float* Wv = (const float*)d_in[9];
    const float* bv = (const float*)d_in[10];
    const float* g1 = (const float*)d_in[11];
    const float* b1 = (const float*)d_in[12];
    const float* Wl = (const float*)d_in[13];
    const float* g2 = (const float*)d_in[15];
    const float* b2 = (const float*)d_in[16];

    int N = in_sizes[0] / CIN;
    int NK = N * KNN;

    cudaFuncSetAttribute(k_mma_gemm, cudaFuncAttributeMaxDynamicSharedMemorySize, SMEM_TOTAL);

    k_pack<<<(N + 255) / 256, 256>>>(xyz_i, N);

    dim3 gk(N / 256, SPLITS);
    k_knn<<<gk, 256>>>(xyz_last, N);
    k_merge<<<(N + 255) / 256, 256>>>(N);

    dim3 gq(N / 128, 3);
    k_mma_gemm<<<gq, 256, SMEM_TOTAL>>>(0, fea_i, fea_last, Wq, Wk, Wv);

    k_stats1<<<NK / 512, 256>>>(N);
    k_finalize<<<1, 128>>>(g1, b1, 0, 0, 1.0f / (float)NK);

    k_mma_gemm<<<NK / 128, 256, SMEM_TOTAL>>>(1, fea_i, fea_last, Wq, Wk, Wl);
    k_finalize<<<1, 128>>>(g2, b2, 256, 256, 1.0f / (float)NK);

    k_out<<<N, 128>>>(bv, (float*)d_out, N);
}

// round 5
// speedup vs baseline: 1.2060x; 1.1871x over previous
#include <cuda_runtime.h>
#include <cuda_bf16.h>
#include <cstdint>

#define CIN 128
#define KNN 16
#define NMAX 8192
#define EPS 1e-5f
#define SLOPE 0.01f
#define PAD 136   // bf16 elements per smem row (stride); conflict-free for frag loads
#define GRID 16
#define NCELL (GRID * GRID * GRID)
#define CELLH (1.0f / GRID)

// ---------------- scratch (static device memory; no allocations) ----------------
__device__ int   g_idx[NMAX * KNN];
__device__ int   g_cellcnt[NCELL];
__device__ int   g_cellstart[NCELL + 1];
__device__ int   g_cellcur[NCELL];
__device__ __align__(16) float4 g_cellpts[NMAX];   // (x,y,z, idx-as-float-bits)
__device__ __align__(16) float g_Q[NMAX * CIN];
__device__ __align__(16) float g_K[NMAX * CIN];
__device__ __align__(16) float g_V[NMAX * CIN];
__device__ __align__(16) float g_w2[(size_t)NMAX * KNN * CIN];
__device__ float g_stat[4 * CIN];   // [0:128)=sum1 [128:256)=sq1 [256:384)=sum2 [384:512)=sq2
__device__ float g_aff[4 * CIN];    // [0:128)=sc1  [128:256)=sh1 [256:384)=sc2  [384:512)=sh2

__device__ __forceinline__ int cell1(float x) {
    int c = (int)(x * (float)GRID);
    return c < 0 ? 0 : (c > GRID - 1 ? GRID - 1 : c);
}

// fp32 -> (bf16 hi, bf16 lo) pair pack
__device__ __forceinline__ void split_pair(float x0, float x1, uint32_t& hp, uint32_t& lp) {
    __nv_bfloat16 h0 = __float2bfloat16(x0);
    __nv_bfloat16 h1 = __float2bfloat16(x1);
    __nv_bfloat16 l0 = __float2bfloat16(x0 - __bfloat162float(h0));
    __nv_bfloat16 l1 = __float2bfloat16(x1 - __bfloat162float(h1));
    hp = ((uint32_t)__bfloat16_as_ushort(h1) << 16) | __bfloat16_as_ushort(h0);
    lp = ((uint32_t)__bfloat16_as_ushort(l1) << 16) | __bfloat16_as_ushort(l0);
}

__device__ __forceinline__ void store_split4(char* hi, char* lo, int r, int c, float4 a) {
    uint32_t h0, l0, h1, l1;
    split_pair(a.x, a.y, h0, l0);
    split_pair(a.z, a.w, h1, l1);
    int off = (r * PAD + c) * 2;
    *(uint32_t*)(hi + off)     = h0;
    *(uint32_t*)(lo + off)     = l0;
    *(uint32_t*)(hi + off + 4) = h1;
    *(uint32_t*)(lo + off + 4) = l1;
}

__device__ __forceinline__ void mma16816(float* d, const uint32_t* a, const uint32_t* b) {
    asm volatile(
        "mma.sync.aligned.m16n8k16.row.col.f32.bf16.bf16.f32 "
        "{%0,%1,%2,%3}, {%4,%5,%6,%7}, {%8,%9}, {%0,%1,%2,%3};"
        : "+f"(d[0]), "+f"(d[1]), "+f"(d[2]), "+f"(d[3])
        : "r"(a[0]), "r"(a[1]), "r"(a[2]), "r"(a[3]), "r"(b[0]), "r"(b[1]));
}

// ---------------- grid build ----------------
__global__ void k_zero() {
    int i = blockIdx.x * 256 + threadIdx.x;
    if (i < NCELL) { g_cellcnt[i] = 0; }
    if (i < 4 * CIN) g_stat[i] = 0.f;
}

__global__ void k_count(const float* __restrict__ xyz_i, int N) {
    int i = blockIdx.x * 256 + threadIdx.x;
    if (i >= N) return;
    int cx = cell1(xyz_i[i * 3 + 0]);
    int cy = cell1(xyz_i[i * 3 + 1]);
    int cz = cell1(xyz_i[i * 3 + 2]);
    atomicAdd(&g_cellcnt[(cz * GRID + cy) * GRID + cx], 1);
}

// single block, 1024 threads, each handles 4 cells
__global__ void k_scan(int N) {
    __shared__ int ssum[1024];
    int t = threadIdx.x;
    int c[4], loc[4];
    int s = 0;
#pragma unroll
    for (int v = 0; v < 4; v++) {
        c[v] = g_cellcnt[4 * t + v];
        loc[v] = s;
        s += c[v];
    }
    ssum[t] = s;
    __syncthreads();
    for (int off = 1; off < 1024; off <<= 1) {
        int v = (t >= off) ? ssum[t - off] : 0;
        __syncthreads();
        ssum[t] += v;
        __syncthreads();
    }
    int base = (t > 0) ? ssum[t - 1] : 0;
#pragma unroll
    for (int v = 0; v < 4; v++) {
        g_cellstart[4 * t + v] = base + loc[v];
        g_cellcur[4 * t + v]   = base + loc[v];
    }
    if (t == 1023) g_cellstart[NCELL] = N;
}

__global__ void k_fill(const float* __restrict__ xyz_i, int N) {
    int i = blockIdx.x * 256 + threadIdx.x;
    if (i >= N) return;
    float x = xyz_i[i * 3 + 0], y = xyz_i[i * 3 + 1], z = xyz_i[i * 3 + 2];
    int cellid = (cell1(z) * GRID + cell1(y)) * GRID + cell1(x);
    int slot = atomicAdd(&g_cellcur[cellid], 1);
    g_cellpts[slot] = make_float4(x, y, z, __int_as_float(i));
}

// ---------------- grid knn: thread-per-query, expanding shells, replace-max top16 ----------------
__global__ void k_knn_grid(const float* __restrict__ xyz_last, int N) {
    int q = blockIdx.x * 64 + threadIdx.x;
    if (q >= N) return;
    float qx = xyz_last[q * 3 + 0];
    float qy = xyz_last[q * 3 + 1];
    float qz = xyz_last[q * 3 + 2];
    int cx = cell1(qx), cy = cell1(qy), cz = cell1(qz);

    float bd[KNN];
    int   bi[KNN];
#pragma unroll
    for (int s = 0; s < KNN; s++) { bd[s] = 1e30f; bi[s] = -1; }
    float curmax = 1e30f;
    int maxslot = 0;

    for (int R = 0; R < GRID; R++) {
        int zlo = cz - R < 0 ? 0 : cz - R, zhi = cz + R > GRID - 1 ? GRID - 1 : cz + R;
        int ylo = cy - R < 0 ? 0 : cy - R, yhi = cy + R > GRID - 1 ? GRID - 1 : cy + R;
        int xlo = cx - R < 0 ? 0 : cx - R, xhi = cx + R > GRID - 1 ? GRID - 1 : cx + R;
        for (int zz = zlo; zz <= zhi; zz++) {
            int adz = zz - cz; adz = adz < 0 ? -adz : adz;
            for (int yy = ylo; yy <= yhi; yy++) {
                int ady = yy - cy; ady = ady < 0 ? -ady : ady;
                int rowmax = adz > ady ? adz : ady;
                for (int xx = xlo; xx <= xhi; xx++) {
                    int adx = xx - cx; adx = adx < 0 ? -adx : adx;
                    int cheb = rowmax > adx ? rowmax : adx;
                    if (cheb != R) continue;   // shell only
                    int cellid = (zz * GRID + yy) * GRID + xx;
                    int s0 = g_cellstart[cellid];
                    int s1 = g_cellstart[cellid + 1];
                    for (int s = s0; s < s1; s++) {
                        float4 p = g_cellpts[s];
                        float dx = qx - p.x, dy = qy - p.y, dz = qz - p.z;
                        float d2 = fmaf(dx, dx, fmaf(dy, dy, dz * dz));
                        if (d2 < curmax) {
                            int j = __float_as_int(p.w);
#pragma unroll
                            for (int t = 0; t < KNN; t++)
                                if (t == maxslot) { bd[t] = d2; bi[t] = j; }
                            curmax = -1.f;
#pragma unroll
                            for (int t = 0; t < KNN; t++)
                                if (bd[t] > curmax) { curmax = bd[t]; maxslot = t; }
                        }
                    }
                }
            }
        }
        float reach = (float)R * CELLH;
        if (curmax <= reach * reach) break;   // all unprocessed cells are farther
    }
#pragma unroll
    for (int s = 0; s < KNN; s++) g_idx[q * KNN + s] = bi[s];
}

// ---------------- mma.sync GEMM: D[128x128] = A[128x128] @ B[128x128]^T ----------------
// mode 0: A rows from fea (blockIdx.y selects Q/K/V), C -> g_Q/g_K/g_V
// mode 1: A row nk = leaky(aff1(Q[n] - K[idx[nk]])), C -> g_w2, fused BN2 stats
// bf16 3-term split: Ah*Bh + Al*Bh + Ah*Bl
#define SM_AHI 0
#define SM_ALO (128 * PAD * 2)
#define SM_BHI (2 * 128 * PAD * 2)
#define SM_BLO (3 * 128 * PAD * 2)
#define SM_AFF (4 * 128 * PAD * 2)        // 256 floats
#define SM_SUM (SM_AFF + 1024)            // 128 floats
#define SM_SQ  (SM_SUM + 512)             // 128 floats
#define SMEM_TOTAL (SM_SQ + 512)

#define LDS32(base, r, col) (*(const uint32_t*)((base) + ((r) * PAD + (col)) * 2))

__global__ void __launch_bounds__(256) k_mma_gemm(
    int mode,
    const float* __restrict__ fea_i, const float* __restrict__ fea_last,
    const float* __restrict__ Wq, const float* __restrict__ Wk,
    const float* __restrict__ Wvl)
{
    extern __shared__ char smem[];
    int t = threadIdx.x;
    int lane = t & 31, wid = t >> 5;
    int g = lane >> 2, c4 = lane & 3;
    int wm = wid & 3, wn = wid >> 2;
    int row0 = blockIdx.x * 128;

    char* Ah = smem + SM_AHI;
    char* Al = smem + SM_ALO;
    char* Bh = smem + SM_BHI;
    char* Bl = smem + SM_BLO;
    float* s_aff = (float*)(smem + SM_AFF);
    float* s_sum = (float*)(smem + SM_SUM);
    float* s_sq  = (float*)(smem + SM_SQ);

    const float* B;
    float* C;
    const float* Asrc = nullptr;
    if (mode == 0) {
        int which = blockIdx.y;
        Asrc = (which == 0) ? fea_last : fea_i;
        B = (which == 0) ? Wq : (which == 1 ? Wk : Wvl);
        C = (which == 0) ? g_Q : (which == 1 ? g_K : g_V);
    } else {
        B = Wvl;
        C = g_w2;
    }

    if (mode == 1 && t < 128) {
        s_aff[t] = g_aff[t];
        s_aff[128 + t] = g_aff[128 + t];
        s_sum[t] = 0.f;
        s_sq[t]  = 0.f;
    }
    if (mode == 1) __syncthreads();

    // ---- prep: thread t handles row r = t>>1, cols (t&1)*64..+63
    {
        int r = t >> 1;
        int ccol = (t & 1) * 64;
        const float4* Br = (const float4*)(B + (size_t)r * 128 + ccol);
#pragma unroll
        for (int v = 0; v < 16; v++)
            store_split4(Bh, Bl, r, ccol + 4 * v, Br[v]);
        if (mode == 0) {
            const float4* Ar = (const float4*)(Asrc + (size_t)(row0 + r) * 128 + ccol);
#pragma unroll
            for (int v = 0; v < 16; v++)
                store_split4(Ah, Al, r, ccol + 4 * v, Ar[v]);
        } else {
            int nk = row0 + r;
            int n = nk >> 4;
            int j = g_idx[nk];
            const float4* Qr = (const float4*)(g_Q + (size_t)n * 128 + ccol);
            const float4* Kr = (const float4*)(g_K + (size_t)j * 128 + ccol);
#pragma unroll
            for (int v = 0; v < 16; v++) {
                float4 a = Qr[v];
                float4 b = Kr[v];
                int cc = ccol + 4 * v;
                float x0 = fmaf(a.x - b.x, s_aff[cc + 0], s_aff[128 + cc + 0]);
                float x1 = fmaf(a.y - b.y, s_aff[cc + 1], s_aff[128 + cc + 1]);
                float x2 = fmaf(a.z - b.z, s_aff[cc + 2], s_aff[128 + cc + 2]);
                float x3 = fmaf(a.w - b.w, s_aff[cc + 3], s_aff[128 + cc + 3]);
                x0 = x0 >= 0.f ? x0 : SLOPE * x0;
                x1 = x1 >= 0.f ? x1 : SLOPE * x1;
                x2 = x2 >= 0.f ? x2 : SLOPE * x2;
                x3 = x3 >= 0.f ? x3 : SLOPE * x3;
                store_split4(Ah, Al, r, cc, make_float4(x0, x1, x2, x3));
            }
        }
    }
    __syncthreads();

    // ---- mma mainloop: warp tile 32(m) x 64(n)
    float acc[2][8][4];
#pragma unroll
    for (int mf = 0; mf < 2; mf++)
#pragma unroll
        for (int nf = 0; nf < 8; nf++)
#pragma unroll
            for (int e = 0; e < 4; e++) acc[mf][nf][e] = 0.f;

#pragma unroll 1
    for (int s = 0; s < 8; s++) {
        int k0 = s * 16;
        uint32_t ah[2][4], al[2][4], bh[8][2], bl[8][2];
#pragma unroll
        for (int mf = 0; mf < 2; mf++) {
            int r = wm * 32 + mf * 16 + g;
            int kc = k0 + 2 * c4;
            ah[mf][0] = LDS32(Ah, r,     kc);
            ah[mf][1] = LDS32(Ah, r + 8, kc);
            ah[mf][2] = LDS32(Ah, r,     kc + 8);
            ah[mf][3] = LDS32(Ah, r + 8, kc + 8);
            al[mf][0] = LDS32(Al, r,     kc);
            al[mf][1] = LDS32(Al, r + 8, kc);
            al[mf][2] = LDS32(Al, r,     kc + 8);
            al[mf][3] = LDS32(Al, r + 8, kc + 8);
        }
#pragma unroll
        for (int nf = 0; nf < 8; nf++) {
            int n = wn * 64 + nf * 8 + g;
            int kc = k0 + 2 * c4;
            bh[nf][0] = LDS32(Bh, n, kc);
            bh[nf][1] = LDS32(Bh, n, kc + 8);
            bl[nf][0] = LDS32(Bl, n, kc);
            bl[nf][1] = LDS32(Bl, n, kc + 8);
        }
#pragma unroll
        for (int mf = 0; mf < 2; mf++)
#pragma unroll
            for (int nf = 0; nf < 8; nf++) {
                mma16816(acc[mf][nf], ah[mf], bh[nf]);
                mma16816(acc[mf][nf], al[mf], bh[nf]);
                mma16816(acc[mf][nf], ah[mf], bl[nf]);
            }
    }

    // ---- epilogue
#pragma unroll
    for (int mf = 0; mf < 2; mf++)
#pragma unroll
        for (int nf = 0; nf < 8; nf++) {
            int row = row0 + wm * 32 + mf * 16 + g;
            int col = wn * 64 + nf * 8 + 2 * c4;
            *(float2*)(C + (size_t)row * 128 + col) =
                make_float2(acc[mf][nf][0], acc[mf][nf][1]);
            *(float2*)(C + (size_t)(row + 8) * 128 + col) =
                make_float2(acc[mf][nf][2], acc[mf][nf][3]);
        }

    if (mode == 1) {
#pragma unroll
        for (int nf = 0; nf < 8; nf++) {
            int col = wn * 64 + nf * 8 + 2 * c4;
            float v00 = acc[0][nf][0], v02 = acc[0][nf][2];
            float v10 = acc[1][nf][0], v12 = acc[1][nf][2];
            atomicAdd(&s_sum[col], v00 + v02 + v10 + v12);
            atomicAdd(&s_sq[col], v00 * v00 + v02 * v02 + v10 * v10 + v12 * v12);
            float v01 = acc[0][nf][1], v03 = acc[0][nf][3];
            float v11 = acc[1][nf][1], v13 = acc[1][nf][3];
            atomicAdd(&s_sum[col + 1], v01 + v03 + v11 + v13);
            atomicAdd(&s_sq[col + 1], v01 * v01 + v03 * v03 + v11 * v11 + v13 * v13);
        }
        __syncthreads();
        if (t < 128) {
            atomicAdd(&g_stat[256 + t], s_sum[t]);
            atomicAdd(&g_stat[384 + t], s_sq[t]);
        }
    }
}

// ---------------- k3: BN1 statistics over w1 = Q[n] - K[idx[n,k]] ----------------
__global__ void k_stats1(int N) {
    int t = threadIdx.x;
    int c = t & 127, g = t >> 7;
    int r0 = blockIdx.x * 512;
    float s = 0.f, q = 0.f;
    for (int r = r0 + g; r < r0 + 512; r += 2) {
        int n = r >> 4;
        int j = g_idx[r];
        float w = g_Q[(size_t)n * 128 + c] - g_K[(size_t)j * 128 + c];
        s += w;
        q = fmaf(w, w, q);
    }
    __shared__ float sh[256];
    sh[t] = s; __syncthreads();
    if (g == 0) atomicAdd(&g_stat[c], sh[c] + sh[128 + c]);
    __syncthreads();
    sh[t] = q; __syncthreads();
    if (g == 0) atomicAdd(&g_stat[128 + c], sh[c] + sh[128 + c]);
}

// ---------------- finalize BN stats -> affine scale/shift ----------------
__global__ void k_finalize(const float* __restrict__ gamma, const float* __restrict__ beta,
                           int soff, int aoff, float inv_cnt) {
    int c = threadIdx.x;
    float mean = g_stat[soff + c] * inv_cnt;
    float var  = g_stat[soff + 128 + c] * inv_cnt - mean * mean;
    float sc = gamma[c] * rsqrtf(var + EPS);
    g_aff[aoff + c] = sc;
    g_aff[aoff + 128 + c] = beta[c] - mean * sc;
}

// ---------------- k7: aff2 + leaky + softmax over K + weighted V sum ----------------
__global__ void k_out(const float* __restrict__ bv, float* __restrict__ out, int N) {
    int n = blockIdx.x;
    int c = threadIdx.x;
    __shared__ int sidx[KNN];
    if (c < KNN) sidx[c] = g_idx[n * KNN + c];
    __syncthreads();

    float sc2 = g_aff[256 + c], sh2 = g_aff[384 + c];
    float tv[KNN];
    float m = -1e30f;
#pragma unroll
    for (int k = 0; k < KNN; k++) {
        float x = g_w2[(size_t)(n * KNN + k) * 128 + c];
        x = fmaf(x, sc2, sh2);
        x = x >= 0.f ? x : SLOPE * x;
        tv[k] = x;
        m = fmaxf(m, x);
    }
    float s = 0.f;
#pragma unroll
    for (int k = 0; k < KNN; k++) { float e = __expf(tv[k] - m); tv[k] = e; s += e; }
    float inv = 1.f / s;
    float b = bv[c];
    float acc = 0.f;
#pragma unroll
    for (int k = 0; k < KNN; k++) {
        float v = g_V[(size_t)sidx[k] * 128 + c] + b;
        acc = fmaf(tv[k] * inv, v, acc);
    }
    out[(size_t)n * 128 + c] = acc;
}

// ---------------- launch ----------------
extern "C" void kernel_launch(void* const* d_in, const int* in_sizes, int n_in,
                              void* d_out, int out_size) {
    const float* fea_i    = (const float*)d_in[0];
    const float* fea_last = (const float*)d_in[1];
    const float* xyz_i    = (const float*)d_in[2];
    const float* xyz_last = (const float*)d_in[3];
    const float* Wq = (const float*)d_in[5];
    const float* Wk = (const float*)d_in[7];
    const float* Wv = (const float*)d_in[9];
    const float* bv = (const float*)d_in[10];
    const float* g1 = (const float*)d_in[11];
    const float* b1 = (const float*)d_in[12];
    const float* Wl = (const float*)d_in[13];
    const float* g2 = (const float*)d_in[15];
    const float* b2 = (const float*)d_in[16];

    int N = in_sizes[0] / CIN;
    int NK = N * KNN;

    cudaFuncSetAttribute(k_mma_gemm, cudaFuncAttributeMaxDynamicSharedMemorySize, SMEM_TOTAL);

    // grid-based exact KNN
    k_zero<<<(NCELL + 255) / 256, 256>>>();
    k_count<<<(N + 255) / 256, 256>>>(xyz_i, N);
    k_scan<<<1, 1024>>>(N);
    k_fill<<<(N + 255) / 256, 256>>>(xyz_i, N);
    k_knn_grid<<<(N + 63) / 64, 64>>>(xyz_last, N);

    dim3 gq(N / 128, 3);
    k_mma_gemm<<<gq, 256, SMEM_TOTAL>>>(0, fea_i, fea_last, Wq, Wk, Wv);

    k_stats1<<<NK / 512, 256>>>(N);
    k_finalize<<<1, 128>>>(g1, b1, 0, 0, 1.0f / (float)NK);

    k_mma_gemm<<<NK / 128, 256, SMEM_TOTAL>>>(1, fea_i, fea_last, Wq, Wk, Wl);
    k_finalize<<<1, 128>>>(g2, b2, 256, 256, 1.0f / (float)NK);

    k_out<<<N, 128>>>(bv, (float*)d_out, N);
}

// round 6
// speedup vs baseline: 1.7301x; 1.4346x over previous
#include <cuda_runtime.h>
#include <cuda_bf16.h>
#include <cstdint>

#define CIN 128
#define KNN 16
#define NMAX 8192
#define EPS 1e-5f
#define SLOPE 0.01f
#define GRID 8
#define NCELL (GRID * GRID * GRID)
#define CELLH (1.0f / GRID)

// ---------------- scratch (static device memory; no allocations) ----------------
__device__ int   g_idx[NMAX * KNN];
__device__ int   g_cellcnt[NCELL];
__device__ int   g_cellstart[NCELL + 1];
__device__ int   g_cellcur[NCELL];
__device__ __align__(16) float4 g_cellpts[NMAX];   // (x,y,z, idx-as-float-bits)
__device__ __align__(16) float g_Q[NMAX * CIN];
__device__ __align__(16) float g_K[NMAX * CIN];
__device__ __align__(16) float g_V[NMAX * CIN];
__device__ __align__(16) float g_w2[(size_t)NMAX * KNN * CIN];
__device__ float g_stat[4 * CIN];   // [0:128)=sum1 [128:256)=sq1 [256:384)=sum2 [384:512)=sq2
__device__ float g_aff[4 * CIN];    // [0:128)=sc1  [128:256)=sh1 [256:384)=sc2  [384:512)=sh2

__device__ __forceinline__ int cell1(float x) {
    int c = (int)(x * (float)GRID);
    return c < 0 ? 0 : (c > GRID - 1 ? GRID - 1 : c);
}

// fp32 -> (bf16 hi, bf16 lo) pair pack
__device__ __forceinline__ void split_pair(float x0, float x1, uint32_t& hp, uint32_t& lp) {
    __nv_bfloat16 h0 = __float2bfloat16(x0);
    __nv_bfloat16 h1 = __float2bfloat16(x1);
    __nv_bfloat16 l0 = __float2bfloat16(x0 - __bfloat162float(h0));
    __nv_bfloat16 l1 = __float2bfloat16(x1 - __bfloat162float(h1));
    hp = ((uint32_t)__bfloat16_as_ushort(h1) << 16) | __bfloat16_as_ushort(h0);
    lp = ((uint32_t)__bfloat16_as_ushort(l1) << 16) | __bfloat16_as_ushort(l0);
}

#define PADK 72   // bf16 stride per row; frag-load banks = 4*g + c4 -> conflict-free

__device__ __forceinline__ void store_split4(char* hi, char* lo, int r, int c, float4 a) {
    uint32_t h0, l0, h1, l1;
    split_pair(a.x, a.y, h0, l0);
    split_pair(a.z, a.w, h1, l1);
    int off = (r * PADK + c) * 2;
    *(uint32_t*)(hi + off)     = h0;
    *(uint32_t*)(lo + off)     = l0;
    *(uint32_t*)(hi + off + 4) = h1;
    *(uint32_t*)(lo + off + 4) = l1;
}

__device__ __forceinline__ void mma16816(float* d, const uint32_t* a, const uint32_t* b) {
    asm volatile(
        "mma.sync.aligned.m16n8k16.row.col.f32.bf16.bf16.f32 "
        "{%0,%1,%2,%3}, {%4,%5,%6,%7}, {%8,%9}, {%0,%1,%2,%3};"
        : "+f"(d[0]), "+f"(d[1]), "+f"(d[2]), "+f"(d[3])
        : "r"(a[0]), "r"(a[1]), "r"(a[2]), "r"(a[3]), "r"(b[0]), "r"(b[1]));
}

// ---------------- grid build ----------------
__global__ void k_zero() {
    int i = threadIdx.x;   // 512
    g_cellcnt[i] = 0;
    g_stat[i] = 0.f;       // 4*CIN == 512
}

__global__ void k_count(const float* __restrict__ xyz_i, int N) {
    int i = blockIdx.x * 256 + threadIdx.x;
    if (i >= N) return;
    int cx = cell1(xyz_i[i * 3 + 0]);
    int cy = cell1(xyz_i[i * 3 + 1]);
    int cz = cell1(xyz_i[i * 3 + 2]);
    atomicAdd(&g_cellcnt[(cz * GRID + cy) * GRID + cx], 1);
}

__global__ void k_scan(int N) {
    __shared__ int ssum[NCELL];
    int t = threadIdx.x;   // 512
    int c = g_cellcnt[t];
    ssum[t] = c;
    __syncthreads();
    for (int o = 1; o < NCELL; o <<= 1) {
        int v = (t >= o) ? ssum[t - o] : 0;
        __syncthreads();
        ssum[t] += v;
        __syncthreads();
    }
    int excl = ssum[t] - c;
    g_cellstart[t] = excl;
    g_cellcur[t]   = excl;
    if (t == NCELL - 1) g_cellstart[NCELL] = ssum[NCELL - 1];
}

__global__ void k_fill(const float* __restrict__ xyz_i, int N) {
    int i = blockIdx.x * 256 + threadIdx.x;
    if (i >= N) return;
    float x = xyz_i[i * 3 + 0], y = xyz_i[i * 3 + 1], z = xyz_i[i * 3 + 2];
    int cellid = (cell1(z) * GRID + cell1(y)) * GRID + cell1(x);
    int slot = atomicAdd(&g_cellcur[cellid], 1);
    g_cellpts[slot] = make_float4(x, y, z, __int_as_float(i));
}

// ---------------- serial fallback knn (exact, shell expansion) ----------------
__device__ void knn_serial(int q, float qx, float qy, float qz, int cx, int cy, int cz) {
    float bd[KNN];
    int   bi[KNN];
#pragma unroll
    for (int s = 0; s < KNN; s++) { bd[s] = 1e30f; bi[s] = -1; }
    float curmax = 1e30f;
    int maxslot = 0;
    for (int R = 0; R < GRID; R++) {
        int zlo = cz - R < 0 ? 0 : cz - R, zhi = cz + R > GRID - 1 ? GRID - 1 : cz + R;
        int ylo = cy - R < 0 ? 0 : cy - R, yhi = cy + R > GRID - 1 ? GRID - 1 : cy + R;
        int xlo = cx - R < 0 ? 0 : cx - R, xhi = cx + R > GRID - 1 ? GRID - 1 : cx + R;
        for (int zz = zlo; zz <= zhi; zz++) {
            int adz = zz - cz; adz = adz < 0 ? -adz : adz;
            for (int yy = ylo; yy <= yhi; yy++) {
                int ady = yy - cy; ady = ady < 0 ? -ady : ady;
                int rowmax = adz > ady ? adz : ady;
                for (int xx = xlo; xx <= xhi; xx++) {
                    int adx = xx - cx; adx = adx < 0 ? -adx : adx;
                    int cheb = rowmax > adx ? rowmax : adx;
                    if (cheb != R) continue;
                    int cellid = (zz * GRID + yy) * GRID + xx;
                    int s0 = g_cellstart[cellid];
                    int s1 = g_cellstart[cellid + 1];
                    for (int s = s0; s < s1; s++) {
                        float4 p = g_cellpts[s];
                        float dx = qx - p.x, dy = qy - p.y, dz = qz - p.z;
                        float d2 = fmaf(dx, dx, fmaf(dy, dy, dz * dz));
                        if (d2 < curmax) {
                            int j = __float_as_int(p.w);
#pragma unroll
                            for (int t = 0; t < KNN; t++)
                                if (t == maxslot) { bd[t] = d2; bi[t] = j; }
                            curmax = -1.f;
#pragma unroll
                            for (int t = 0; t < KNN; t++)
                                if (bd[t] > curmax) { curmax = bd[t]; maxslot = t; }
                        }
                    }
                }
            }
        }
        float reach = (float)R * CELLH;
        if (curmax <= reach * reach) break;
    }
#pragma unroll
    for (int s = 0; s < KNN; s++) g_idx[q * KNN + s] = bi[s];
}

// ---------------- warp-per-query knn over the 3x3x3 cell cube ----------------
__global__ void __launch_bounds__(256) k_knn_warp(const float* __restrict__ xyz_last, int N) {
    int warp = (blockIdx.x * 256 + threadIdx.x) >> 5;
    int lid = threadIdx.x & 31;
    if (warp >= N) return;
    int q = warp;
    float qx = xyz_last[q * 3 + 0];
    float qy = xyz_last[q * 3 + 1];
    float qz = xyz_last[q * 3 + 2];
    int cx = cell1(qx), cy = cell1(qy), cz = cell1(qz);

    int zlo = cz - 1 < 0 ? 0 : cz - 1, zhi = cz + 1 > GRID - 1 ? GRID - 1 : cz + 1;
    int ylo = cy - 1 < 0 ? 0 : cy - 1, yhi = cy + 1 > GRID - 1 ? GRID - 1 : cy + 1;
    int xlo = cx - 1 < 0 ? 0 : cx - 1, xhi = cx + 1 > GRID - 1 ? GRID - 1 : cx + 1;
    int ny = yhi - ylo + 1;
    int nrows = (zhi - zlo + 1) * ny;

    // lane l < nrows owns one x-contiguous row of cells
    int s0 = 0, len = 0;
    if (lid < nrows) {
        int zz = zlo + lid / ny;
        int yy = ylo + lid % ny;
        int cbase = (zz * GRID + yy) * GRID;
        s0 = g_cellstart[cbase + xlo];
        len = g_cellstart[cbase + xhi + 1] - s0;
    }
    // exclusive prefix of len across lanes
    int pre = len;
#pragma unroll
    for (int o = 1; o < 32; o <<= 1) {
        int v = __shfl_up_sync(0xFFFFFFFFu, pre, o);
        if (lid >= o) pre += v;
    }
    int T = __shfl_sync(0xFFFFFFFFu, pre, 31);
    int myStart = pre - len;

    // per-lane top-16 collection over strided candidates
    float bd[KNN];
    int   bi[KNN];
#pragma unroll
    for (int s = 0; s < KNN; s++) { bd[s] = 1e30f; bi[s] = -1; }
    float curmax = 1e30f;
    int maxslot = 0;

    int niter = (T + 31) >> 5;
    for (int it = 0; it < niter; it++) {
        int c = it * 32 + lid;
        int slot = -1;
        for (int j = 0; j < nrows; j++) {
            int pj = __shfl_sync(0xFFFFFFFFu, myStart, j);
            int lj = __shfl_sync(0xFFFFFFFFu, len, j);
            int sj = __shfl_sync(0xFFFFFFFFu, s0, j);
            if (c >= pj && c < pj + lj) slot = sj + (c - pj);
        }
        if (c < T && slot >= 0) {
            float4 p = g_cellpts[slot];
            float dx = qx - p.x, dy = qy - p.y, dz = qz - p.z;
            float d2 = fmaf(dx, dx, fmaf(dy, dy, dz * dz));
            if (d2 < curmax) {
                int j = __float_as_int(p.w);
#pragma unroll
                for (int t = 0; t < KNN; t++)
                    if (t == maxslot) { bd[t] = d2; bi[t] = j; }
                curmax = -1.f;
#pragma unroll
                for (int t = 0; t < KNN; t++)
                    if (bd[t] > curmax) { curmax = bd[t]; maxslot = t; }
            }
        }
    }

    // 16-round warp argmin extraction
    float lmin = 1e30f;
    int lslot = 0;
#pragma unroll
    for (int s = 0; s < KNN; s++)
        if (bd[s] < lmin) { lmin = bd[s]; lslot = s; }

    float d16 = 0.f;
    int myres = -1;
    for (int r = 0; r < KNN; r++) {
        float v = lmin;
        int wl = lid;
#pragma unroll
        for (int o = 16; o; o >>= 1) {
            float ov = __shfl_xor_sync(0xFFFFFFFFu, v, o);
            int owl = __shfl_xor_sync(0xFFFFFFFFu, wl, o);
            if (ov < v || (ov == v && owl < wl)) { v = ov; wl = owl; }
        }
        int myidx = -1;
#pragma unroll
        for (int s = 0; s < KNN; s++)
            if (s == lslot) myidx = bi[s];
        int wi = __shfl_sync(0xFFFFFFFFu, myidx, wl);
        d16 = v;
        if (lid == r) myres = wi;
        if (lid == wl) {
#pragma unroll
            for (int s = 0; s < KNN; s++)
                if (s == lslot) bd[s] = 1e30f;
            lmin = 1e30f; lslot = 0;
#pragma unroll
            for (int s = 0; s < KNN; s++)
                if (bd[s] < lmin) { lmin = bd[s]; lslot = s; }
        }
    }

    if (d16 <= CELLH * CELLH) {
        if (lid < KNN) g_idx[q * KNN + lid] = myres;   // exact: all unvisited cells >= CELLH away
    } else {
        if (lid == 0) knn_serial(q, qx, qy, qz, cx, cy, cz);  // rare boundary case
    }
}

// ---------------- mma.sync GEMM, K-tiled (BK=64, 2 passes) ----------------
// mode 0: A rows from fea (blockIdx.y selects Q/K/V), C -> g_Q/g_K/g_V
// mode 1: A row nk = leaky(aff1(Q[n] - K[idx[nk]])), C -> g_w2, fused BN2 stats
// bf16 3-term split: Ah*Bh + Al*Bh + Ah*Bl
#define TILEB (128 * PADK * 2)            // 18432
#define SM_AHI 0
#define SM_ALO TILEB
#define SM_BHI (2 * TILEB)
#define SM_BLO (3 * TILEB)
#define SM_AFF (4 * TILEB)                // 256 floats
#define SM_SUM (SM_AFF + 1024)            // 128 floats
#define SM_SQ  (SM_SUM + 512)             // 128 floats
#define SMEM_TOTAL (SM_SQ + 512)          // ~74 KB -> 2 blocks/SM (reg-limited)

#define LDS32(base, r, col) (*(const uint32_t*)((base) + ((r) * PADK + (col)) * 2))

__global__ void __launch_bounds__(256, 2) k_mma_gemm(
    int mode,
    const float* __restrict__ fea_i, const float* __restrict__ fea_last,
    const float* __restrict__ Wq, const float* __restrict__ Wk,
    const float* __restrict__ Wvl)
{
    extern __shared__ char smem[];
    int t = threadIdx.x;
    int lane = t & 31, wid = t >> 5;
    int g = lane >> 2, c4 = lane & 3;
    int wm = wid & 3, wn = wid >> 2;
    int row0 = blockIdx.x * 128;

    char* Ah = smem + SM_AHI;
    char* Al = smem + SM_ALO;
    char* Bh = smem + SM_BHI;
    char* Bl = smem + SM_BLO;
    float* s_aff = (float*)(smem + SM_AFF);
    float* s_sum = (float*)(smem + SM_SUM);
    float* s_sq  = (float*)(smem + SM_SQ);

    const float* B;
    float* C;
    const float* Asrc = nullptr;
    if (mode == 0) {
        int which = blockIdx.y;
        Asrc = (which == 0) ? fea_last : fea_i;
        B = (which == 0) ? Wq : (which == 1 ? Wk : Wvl);
        C = (which == 0) ? g_Q : (which == 1 ? g_K : g_V);
    } else {
        B = Wvl;
        C = g_w2;
    }

    if (mode == 1 && t < 128) {
        s_aff[t] = g_aff[t];
        s_aff[128 + t] = g_aff[128 + t];
        s_sum[t] = 0.f;
        s_sq[t]  = 0.f;
    }
    if (mode == 1) __syncthreads();

    float acc[2][8][4];
#pragma unroll
    for (int mf = 0; mf < 2; mf++)
#pragma unroll
        for (int nf = 0; nf < 8; nf++)
#pragma unroll
            for (int e = 0; e < 4; e++) acc[mf][nf][e] = 0.f;

    int pr = t >> 1;             // prep row
    int pch = (t & 1) * 32;      // prep col chunk (local)
    int pn = -1, pj = -1;
    if (mode == 1) {
        int nk = row0 + pr;
        pn = nk >> 4;
        pj = g_idx[nk];
    }

#pragma unroll 1
    for (int pass = 0; pass < 2; pass++) {
        int kk0 = pass * 64;
        // ---- prep this K-slice
        {
            const float4* Br = (const float4*)(B + (size_t)pr * 128 + kk0 + pch);
#pragma unroll
            for (int v = 0; v < 8; v++)
                store_split4(Bh, Bl, pr, pch + 4 * v, Br[v]);
            if (mode == 0) {
                const float4* Ar = (const float4*)(Asrc + (size_t)(row0 + pr) * 128 + kk0 + pch);
#pragma unroll
                for (int v = 0; v < 8; v++)
                    store_split4(Ah, Al, pr, pch + 4 * v, Ar[v]);
            } else {
                const float4* Qr = (const float4*)(g_Q + (size_t)pn * 128 + kk0 + pch);
                const float4* Kr = (const float4*)(g_K + (size_t)pj * 128 + kk0 + pch);
#pragma unroll
                for (int v = 0; v < 8; v++) {
                    float4 a = Qr[v];
                    float4 b = Kr[v];
                    int cg = kk0 + pch + 4 * v;   // global channel
                    float x0 = fmaf(a.x - b.x, s_aff[cg + 0], s_aff[128 + cg + 0]);
                    float x1 = fmaf(a.y - b.y, s_aff[cg + 1], s_aff[128 + cg + 1]);
                    float x2 = fmaf(a.z - b.z, s_aff[cg + 2], s_aff[128 + cg + 2]);
                    float x3 = fmaf(a.w - b.w, s_aff[cg + 3], s_aff[128 + cg + 3]);
                    x0 = x0 >= 0.f ? x0 : SLOPE * x0;
                    x1 = x1 >= 0.f ? x1 : SLOPE * x1;
                    x2 = x2 >= 0.f ? x2 : SLOPE * x2;
                    x3 = x3 >= 0.f ? x3 : SLOPE * x3;
                    store_split4(Ah, Al, pr, pch + 4 * v, make_float4(x0, x1, x2, x3));
                }
            }
        }
        __syncthreads();

        // ---- 4 K-steps of 16
#pragma unroll
        for (int s = 0; s < 4; s++) {
            int kc = s * 16 + 2 * c4;
            uint32_t ah[2][4], al[2][4], bh[8][2], bl[8][2];
#pragma unroll
            for (int mf = 0; mf < 2; mf++) {
                int r = wm * 32 + mf * 16 + g;
                ah[mf][0] = LDS32(Ah, r,     kc);
                ah[mf][1] = LDS32(Ah, r + 8, kc);
                ah[mf][2] = LDS32(Ah, r,     kc + 8);
                ah[mf][3] = LDS32(Ah, r + 8, kc + 8);
                al[mf][0] = LDS32(Al, r,     kc);
                al[mf][1] = LDS32(Al, r + 8, kc);
                al[mf][2] = LDS32(Al, r,     kc + 8);
                al[mf][3] = LDS32(Al, r + 8, kc + 8);
            }
#pragma unroll
            for (int nf = 0; nf < 8; nf++) {
                int n = wn * 64 + nf * 8 + g;
                bh[nf][0] = LDS32(Bh, n, kc);
                bh[nf][1] = LDS32(Bh, n, kc + 8);
                bl[nf][0] = LDS32(Bl, n, kc);
                bl[nf][1] = LDS32(Bl, n, kc + 8);
            }
#pragma unroll
            for (int mf = 0; mf < 2; mf++)
#pragma unroll
                for (int nf = 0; nf < 8; nf++) {
                    mma16816(acc[mf][nf], ah[mf], bh[nf]);
                    mma16816(acc[mf][nf], al[mf], bh[nf]);
                    mma16816(acc[mf][nf], ah[mf], bl[nf]);
                }
        }
        __syncthreads();
    }

    // ---- epilogue
#pragma unroll
    for (int mf = 0; mf < 2; mf++)
#pragma unroll
        for (int nf = 0; nf < 8; nf++) {
            int row = row0 + wm * 32 + mf * 16 + g;
            int col = wn * 64 + nf * 8 + 2 * c4;
            *(float2*)(C + (size_t)row * 128 + col) =
                make_float2(acc[mf][nf][0], acc[mf][nf][1]);
            *(float2*)(C + (size_t)(row + 8) * 128 + col) =
                make_float2(acc[mf][nf][2], acc[mf][nf][3]);
        }

    if (mode == 1) {
#pragma unroll
        for (int nf = 0; nf < 8; nf++) {
            int col = wn * 64 + nf * 8 + 2 * c4;
            float v00 = acc[0][nf][0], v02 = acc[0][nf][2];
            float v10 = acc[1][nf][0], v12 = acc[1][nf][2];
            atomicAdd(&s_sum[col], v00 + v02 + v10 + v12);
            atomicAdd(&s_sq[col], v00 * v00 + v02 * v02 + v10 * v10 + v12 * v12);
            float v01 = acc[0][nf][1], v03 = acc[0][nf][3];
            float v11 = acc[1][nf][1], v13 = acc[1][nf][3];
            atomicAdd(&s_sum[col + 1], v01 + v03 + v11 + v13);
            atomicAdd(&s_sq[col + 1], v01 * v01 + v03 * v03 + v11 * v11 + v13 * v13);
        }
        __syncthreads();
        if (t < 128) {
            atomicAdd(&g_stat[256 + t], s_sum[t]);
            atomicAdd(&g_stat[384 + t], s_sq[t]);
        }
    }
}

// ---------------- k3: BN1 statistics over w1 = Q[n] - K[idx[n,k]] ----------------
__global__ void k_stats1(int N) {
    int t = threadIdx.x;
    int c = t & 127, g = t >> 7;
    int r0 = blockIdx.x * 512;
    float s = 0.f, q = 0.f;
    for (int r = r0 + g; r < r0 + 512; r += 2) {
        int n = r >> 4;
        int j = g_idx[r];
        float w = g_Q[(size_t)n * 128 + c] - g_K[(size_t)j * 128 + c];
        s += w;
        q = fmaf(w, w, q);
    }
    __shared__ float sh[256];
    sh[t] = s; __syncthreads();
    if (g == 0) atomicAdd(&g_stat[c], sh[c] + sh[128 + c]);
    __syncthreads();
    sh[t] = q; __syncthreads();
    if (g == 0) atomicAdd(&g_stat[128 + c], sh[c] + sh[128 + c]);
}

// ---------------- finalize BN stats -> affine scale/shift ----------------
__global__ void k_finalize(const float* __restrict__ gamma, const float* __restrict__ beta,
                           int soff, int aoff, float inv_cnt) {
    int c = threadIdx.x;
    float mean = g_stat[soff + c] * inv_cnt;
    float var  = g_stat[soff + 128 + c] * inv_cnt - mean * mean;
    float sc = gamma[c] * rsqrtf(var + EPS);
    g_aff[aoff + c] = sc;
    g_aff[aoff + 128 + c] = beta[c] - mean * sc;
}

// ---------------- k7: aff2 + leaky + softmax over K + weighted V sum ----------------
__global__ void k_out(const float* __restrict__ bv, float* __restrict__ out, int N) {
    int n = blockIdx.x;
    int c = threadIdx.x;
    __shared__ int sidx[KNN];
    if (c < KNN) sidx[c] = g_idx[n * KNN + c];
    __syncthreads();

    float sc2 = g_aff[256 + c], sh2 = g_aff[384 + c];
    float tv[KNN];
    float m = -1e30f;
#pragma unroll
    for (int k = 0; k < KNN; k++) {
        float x = g_w2[(size_t)(n * KNN + k) * 128 + c];
        x = fmaf(x, sc2, sh2);
        x = x >= 0.f ? x : SLOPE * x;
        tv[k] = x;
        m = fmaxf(m, x);
    }
    float s = 0.f;
#pragma unroll
    for (int k = 0; k < KNN; k++) { float e = __expf(tv[k] - m); tv[k] = e; s += e; }
    float inv = 1.f / s;
    float b = bv[c];
    float acc = 0.f;
#pragma unroll
    for (int k = 0; k < KNN; k++) {
        float v = g_V[(size_t)sidx[k] * 128 + c] + b;
        acc = fmaf(tv[k] * inv, v, acc);
    }
    out[(size_t)n * 128 + c] = acc;
}

// ---------------- launch ----------------
extern "C" void kernel_launch(void* const* d_in, const int* in_sizes, int n_in,
                              void* d_out, int out_size) {
    const float* fea_i    = (const float*)d_in[0];
    const float* fea_last = (const float*)d_in[1];
    const float* xyz_i    = (const float*)d_in[2];
    const float* xyz_last = (const float*)d_in[3];
    const float* Wq = (const float*)d_in[5];
    const float* Wk = (const float*)d_in[7];
    const float* Wv = (const float*)d_in[9];
    const float* bv = (const float*)d_in[10];
    const float* g1 = (const float*)d_in[11];
    const float* b1 = (const float*)d_in[12];
    const float* Wl = (const float*)d_in[13];
    const float* g2 = (const float*)d_in[15];
    const float* b2 = (const float*)d_in[16];

    int N = in_sizes[0] / CIN;
    int NK = N * KNN;

    cudaFuncSetAttribute(k_mma_gemm, cudaFuncAttributeMaxDynamicSharedMemorySize, SMEM_TOTAL);

    // grid-based exact KNN (GRID=8, warp-per-query)
    k_zero<<<1, NCELL>>>();
    k_count<<<(N + 255) / 256, 256>>>(xyz_i, N);
    k_scan<<<1, NCELL>>>(N);
    k_fill<<<(N + 255) / 256, 256>>>(xyz_i, N);
    k_knn_warp<<<(N + 7) / 8, 256>>>(xyz_last, N);

    dim3 gq(N / 128, 3);
    k_mma_gemm<<<gq, 256, SMEM_TOTAL>>>(0, fea_i, fea_last, Wq, Wk, Wv);

    k_stats1<<<NK / 512, 256>>>(N);
    k_finalize<<<1, 128>>>(g1, b1, 0, 0, 1.0f / (float)NK);

    k_mma_gemm<<<NK / 128, 256, SMEM_TOTAL>>>(1, fea_i, fea_last, Wq, Wk, Wl);
    k_finalize<<<1, 128>>>(g2, b2, 256, 256, 1.0f / (float)NK);

    k_out<<<N, 128>>>(bv, (float*)d_out, N);
}

// round 7
// speedup vs baseline: 1.7388x; 1.0050x over previous
#include <cuda_runtime.h>
#include <cuda_bf16.h>
#include <cstdint>

#define CIN 128
#define KNN 16
#define NMAX 8192
#define EPS 1e-5f
#define SLOPE 0.01f
#define GRID 8
#define NCELL (GRID * GRID * GRID)
#define CELLH (1.0f / GRID)
#define PADK 72   // bf16 stride per smem row; frag-load banks 4*g + c4 -> conflict-free

// ---------------- scratch (static device memory; no allocations) ----------------
__device__ int   g_idx[NMAX * KNN];
__device__ int   g_cid[NMAX];
__device__ int   g_cellstart[NCELL + 1];
__device__ __align__(16) float4 g_cellpts[NMAX];   // (x,y,z, idx-as-float-bits)
__device__ __align__(16) float g_Q[NMAX * CIN];
__device__ __align__(16) float g_K[NMAX * CIN];
__device__ __align__(16) float g_V[NMAX * CIN];
__device__ __align__(16) float g_w2[(size_t)NMAX * KNN * CIN];
__device__ float g_stat[4 * CIN];   // [0:128)=sum1 [128:256)=sq1 [256:384)=sum2 [384:512)=sq2
__device__ __align__(16) __nv_bfloat16 g_Wbh[4 * CIN * CIN];  // weight splits hi (Wq,Wk,Wv,Wl)
__device__ __align__(16) __nv_bfloat16 g_Wbl[4 * CIN * CIN];  // weight splits lo

__device__ __forceinline__ int cell1(float x) {
    int c = (int)(x * (float)GRID);
    return c < 0 ? 0 : (c > GRID - 1 ? GRID - 1 : c);
}

__device__ __forceinline__ uint32_t smem_u32(const void* p) {
    uint32_t a;
    asm("{ .reg .u64 t; cvta.to.shared.u64 t, %1; cvt.u32.u64 %0, t; }" : "=r"(a) : "l"(p));
    return a;
}
__device__ __forceinline__ void cp16(uint32_t dst, const void* src) {
    asm volatile("cp.async.cg.shared.global [%0], [%1], 16;" :: "r"(dst), "l"(src));
}
#define CP_COMMIT() asm volatile("cp.async.commit_group;")
#define CP_WAIT0()  asm volatile("cp.async.wait_group 0;" ::: "memory")

// fp32 -> (bf16 hi, bf16 lo) pair pack
__device__ __forceinline__ void split_pair(float x0, float x1, uint32_t& hp, uint32_t& lp) {
    __nv_bfloat16 h0 = __float2bfloat16(x0);
    __nv_bfloat16 h1 = __float2bfloat16(x1);
    __nv_bfloat16 l0 = __float2bfloat16(x0 - __bfloat162float(h0));
    __nv_bfloat16 l1 = __float2bfloat16(x1 - __bfloat162float(h1));
    hp = ((uint32_t)__bfloat16_as_ushort(h1) << 16) | __bfloat16_as_ushort(h0);
    lp = ((uint32_t)__bfloat16_as_ushort(l1) << 16) | __bfloat16_as_ushort(l0);
}

__device__ __forceinline__ void store_split4(char* hi, char* lo, int r, int c, float4 a) {
    uint32_t h0, l0, h1, l1;
    split_pair(a.x, a.y, h0, l0);
    split_pair(a.z, a.w, h1, l1);
    int off = (r * PADK + c) * 2;
    *(uint32_t*)(hi + off)     = h0;
    *(uint32_t*)(lo + off)     = l0;
    *(uint32_t*)(hi + off + 4) = h1;
    *(uint32_t*)(lo + off + 4) = l1;
}

__device__ __forceinline__ void mma16816(float* d, const uint32_t* a, const uint32_t* b) {
    asm volatile(
        "mma.sync.aligned.m16n8k16.row.col.f32.bf16.bf16.f32 "
        "{%0,%1,%2,%3}, {%4,%5,%6,%7}, {%8,%9}, {%0,%1,%2,%3};"
        : "+f"(d[0]), "+f"(d[1]), "+f"(d[2]), "+f"(d[3])
        : "r"(a[0]), "r"(a[1]), "r"(a[2]), "r"(a[3]), "r"(b[0]), "r"(b[1]));
}

// ---------------- k_build: zero stats + weight presplit + grid count/scan/fill ----
// single block, 1024 threads
__global__ void __launch_bounds__(1024) k_build(
    const float* __restrict__ xyz_i,
    const float* __restrict__ Wq, const float* __restrict__ Wk,
    const float* __restrict__ Wv, const float* __restrict__ Wl, int N)
{
    __shared__ int scnt[NCELL];
    __shared__ int spre[NCELL];
    __shared__ int scur[NCELL];
    int t = threadIdx.x;

    if (t < NCELL) scnt[t] = 0;
    if (t < 4 * CIN) g_stat[t] = 0.f;

    // weight presplit: 4 matrices x 16384 elems, 2 elems per iter
    {
        uint32_t* oh = (uint32_t*)g_Wbh;
        uint32_t* ol = (uint32_t*)g_Wbl;
        for (int e = t; e < 4 * CIN * CIN / 2; e += 1024) {
            int m = e >> 13;            // matrix id (8192 pairs per matrix)
            int off = (e & 8191) * 2;   // element offset within matrix
            const float* W = (m == 0) ? Wq : (m == 1 ? Wk : (m == 2 ? Wv : Wl));
            float2 v = *(const float2*)(W + off);
            uint32_t hp, lp;
            split_pair(v.x, v.y, hp, lp);
            oh[e] = hp;
            ol[e] = lp;
        }
    }
    __syncthreads();

    // count
    for (int i = t; i < N; i += 1024) {
        float x = xyz_i[i * 3 + 0], y = xyz_i[i * 3 + 1], z = xyz_i[i * 3 + 2];
        int cid = (cell1(z) * GRID + cell1(y)) * GRID + cell1(x);
        g_cid[i] = cid;
        atomicAdd(&scnt[cid], 1);
    }
    __syncthreads();

    // inclusive scan over NCELL (Hillis-Steele), uniform control flow
    if (t < NCELL) spre[t] = scnt[t];
    __syncthreads();
    for (int o = 1; o < NCELL; o <<= 1) {
        int v = (t >= o && t < NCELL) ? spre[t - o] : 0;
        __syncthreads();
        if (t < NCELL) spre[t] += v;
        __syncthreads();
    }
    if (t < NCELL) {
        int excl = spre[t] - scnt[t];
        g_cellstart[t] = excl;
        scur[t] = excl;
    }
    if (t == NCELL - 1) g_cellstart[NCELL] = spre[NCELL - 1];
    __syncthreads();

    // fill
    for (int i = t; i < N; i += 1024) {
        float x = xyz_i[i * 3 + 0], y = xyz_i[i * 3 + 1], z = xyz_i[i * 3 + 2];
        int slot = atomicAdd(&scur[g_cid[i]], 1);
        g_cellpts[slot] = make_float4(x, y, z, __int_as_float(i));
    }
}

// ---------------- serial fallback knn (exact, shell expansion) ----------------
__device__ void knn_serial(int q, float qx, float qy, float qz, int cx, int cy, int cz) {
    float bd[KNN];
    int   bi[KNN];
#pragma unroll
    for (int s = 0; s < KNN; s++) { bd[s] = 1e30f; bi[s] = -1; }
    float curmax = 1e30f;
    int maxslot = 0;
    for (int R = 0; R < GRID; R++) {
        int zlo = cz - R < 0 ? 0 : cz - R, zhi = cz + R > GRID - 1 ? GRID - 1 : cz + R;
        int ylo = cy - R < 0 ? 0 : cy - R, yhi = cy + R > GRID - 1 ? GRID - 1 : cy + R;
        int xlo = cx - R < 0 ? 0 : cx - R, xhi = cx + R > GRID - 1 ? GRID - 1 : cx + R;
        for (int zz = zlo; zz <= zhi; zz++) {
            int adz = zz - cz; adz = adz < 0 ? -adz : adz;
            for (int yy = ylo; yy <= yhi; yy++) {
                int ady = yy - cy; ady = ady < 0 ? -ady : ady;
                int rowmax = adz > ady ? adz : ady;
                for (int xx = xlo; xx <= xhi; xx++) {
                    int adx = xx - cx; adx = adx < 0 ? -adx : adx;
                    int cheb = rowmax > adx ? rowmax : adx;
                    if (cheb != R) continue;
                    int cellid = (zz * GRID + yy) * GRID + xx;
                    int s0 = g_cellstart[cellid];
                    int s1 = g_cellstart[cellid + 1];
                    for (int s = s0; s < s1; s++) {
                        float4 p = g_cellpts[s];
                        float dx = qx - p.x, dy = qy - p.y, dz = qz - p.z;
                        float d2 = fmaf(dx, dx, fmaf(dy, dy, dz * dz));
                        if (d2 < curmax) {
                            int j = __float_as_int(p.w);
#pragma unroll
                            for (int u = 0; u < KNN; u++)
                                if (u == maxslot) { bd[u] = d2; bi[u] = j; }
                            curmax = -1.f;
#pragma unroll
                            for (int u = 0; u < KNN; u++)
                                if (bd[u] > curmax) { curmax = bd[u]; maxslot = u; }
                        }
                    }
                }
            }
        }
        float reach = (float)R * CELLH;
        if (curmax <= reach * reach) break;
    }
#pragma unroll
    for (int s = 0; s < KNN; s++) g_idx[q * KNN + s] = bi[s];
}

// ---------------- warp-per-query knn over the 3x3x3 cell cube ----------------
__global__ void __launch_bounds__(256) k_knn_warp(const float* __restrict__ xyz_last, int N) {
    __shared__ int s_pre[8][12];
    __shared__ int s_s0[8][12];
    int w = threadIdx.x >> 5;
    int lid = threadIdx.x & 31;
    int q = (blockIdx.x * 256 + threadIdx.x) >> 5;
    if (q >= N) return;
    float qx = xyz_last[q * 3 + 0];
    float qy = xyz_last[q * 3 + 1];
    float qz = xyz_last[q * 3 + 2];
    int cx = cell1(qx), cy = cell1(qy), cz = cell1(qz);

    int zlo = cz - 1 < 0 ? 0 : cz - 1, zhi = cz + 1 > GRID - 1 ? GRID - 1 : cz + 1;
    int ylo = cy - 1 < 0 ? 0 : cy - 1, yhi = cy + 1 > GRID - 1 ? GRID - 1 : cy + 1;
    int xlo = cx - 1 < 0 ? 0 : cx - 1, xhi = cx + 1 > GRID - 1 ? GRID - 1 : cx + 1;
    int ny = yhi - ylo + 1;
    int nrows = (zhi - zlo + 1) * ny;   // <= 9

    int s0 = 0, len = 0;
    if (lid < nrows) {
        int zz = zlo + lid / ny;
        int yy = ylo + lid % ny;
        int cbase = (zz * GRID + yy) * GRID;
        s0 = g_cellstart[cbase + xlo];
        len = g_cellstart[cbase + xhi + 1] - s0;
    }
    // exclusive prefix of len across lanes
    int pre = len;
#pragma unroll
    for (int o = 1; o < 32; o <<= 1) {
        int v = __shfl_up_sync(0xFFFFFFFFu, pre, o);
        if (lid >= o) pre += v;
    }
    int T = __shfl_sync(0xFFFFFFFFu, pre, 31);
    int myStart = pre - len;

    // publish row table to smem (branchless lookup later)
    if (lid < 12) { s_pre[w][lid] = 0x7FFFFFFF; s_s0[w][lid] = 0; }
    __syncwarp();
    if (lid <= nrows && lid < 10) s_pre[w][lid] = myStart;   // lid==nrows holds T
    if (lid < nrows) s_s0[w][lid] = s0;
    __syncwarp();

    float bd[KNN];
    int   bi[KNN];
#pragma unroll
    for (int s = 0; s < KNN; s++) { bd[s] = 1e30f; bi[s] = -1; }
    float curmax = 1e30f;
    int maxslot = 0;

    int niter = (T + 31) >> 5;
    for (int it = 0; it < niter; it++) {
        int c = it * 32 + lid;
        if (c < T) {
            int j = 0;
#pragma unroll
            for (int i = 1; i <= 9; i++) j += (c >= s_pre[w][i]) ? 1 : 0;
            int slot = s_s0[w][j] + (c - s_pre[w][j]);
            float4 p = g_cellpts[slot];
            float dx = qx - p.x, dy = qy - p.y, dz = qz - p.z;
            float d2 = fmaf(dx, dx, fmaf(dy, dy, dz * dz));
            if (d2 < curmax) {
                int ji = __float_as_int(p.w);
#pragma unroll
                for (int u = 0; u < KNN; u++)
                    if (u == maxslot) { bd[u] = d2; bi[u] = ji; }
                curmax = -1.f;
#pragma unroll
                for (int u = 0; u < KNN; u++)
                    if (bd[u] > curmax) { curmax = bd[u]; maxslot = u; }
            }
        }
    }

    // 16-round warp argmin extraction
    float lmin = 1e30f;
    int lslot = 0;
#pragma unroll
    for (int s = 0; s < KNN; s++)
        if (bd[s] < lmin) { lmin = bd[s]; lslot = s; }

    float d16 = 0.f;
    int myres = -1;
    for (int r = 0; r < KNN; r++) {
        float v = lmin;
        int wl = lid;
#pragma unroll
        for (int o = 16; o; o >>= 1) {
            float ov = __shfl_xor_sync(0xFFFFFFFFu, v, o);
            int owl = __shfl_xor_sync(0xFFFFFFFFu, wl, o);
            if (ov < v || (ov == v && owl < wl)) { v = ov; wl = owl; }
        }
        int myidx = -1;
#pragma unroll
        for (int s = 0; s < KNN; s++)
            if (s == lslot) myidx = bi[s];
        int wi = __shfl_sync(0xFFFFFFFFu, myidx, wl);
        d16 = v;
        if (lid == r) myres = wi;
        if (lid == wl) {
#pragma unroll
            for (int s = 0; s < KNN; s++)
                if (s == lslot) bd[s] = 1e30f;
            lmin = 1e30f; lslot = 0;
#pragma unroll
            for (int s = 0; s < KNN; s++)
                if (bd[s] < lmin) { lmin = bd[s]; lslot = s; }
        }
    }

    if (d16 <= CELLH * CELLH) {
        if (lid < KNN) g_idx[q * KNN + lid] = myres;   // exact: unvisited cells >= CELLH away
    } else {
        if (lid == 0) knn_serial(q, qx, qy, qz, cx, cy, cz);  // rare boundary case
    }
}

// ---------------- mma.sync GEMM, K-tiled (BK=64, 2 passes), B via cp.async presplit --
#define TILEB (128 * PADK * 2)            // 18432
#define SM_AHI 0
#define SM_ALO TILEB
#define SM_BHI (2 * TILEB)
#define SM_BLO (3 * TILEB)
#define SM_AFF (4 * TILEB)                // 256 floats
#define SM_SUM (SM_AFF + 1024)            // 128 floats
#define SM_SQ  (SM_SUM + 512)             // 128 floats
#define SMEM_TOTAL (SM_SQ + 512)          // ~74 KB -> 2 blocks/SM (reg-limited)

#define LDS32(base, r, col) (*(const uint32_t*)((base) + ((r) * PADK + (col)) * 2))

__global__ void __launch_bounds__(256, 2) k_mma_gemm(
    int mode,
    const float* __restrict__ fea_i, const float* __restrict__ fea_last,
    const float* __restrict__ g1, const float* __restrict__ b1, float invc)
{
    extern __shared__ char smem[];
    int t = threadIdx.x;
    int lane = t & 31, wid = t >> 5;
    int g = lane >> 2, c4 = lane & 3;
    int wm = wid & 3, wn = wid >> 2;
    int row0 = blockIdx.x * 128;

    char* Ah = smem + SM_AHI;
    char* Al = smem + SM_ALO;
    char* Bh = smem + SM_BHI;
    char* Bl = smem + SM_BLO;
    float* s_aff = (float*)(smem + SM_AFF);
    float* s_sum = (float*)(smem + SM_SUM);
    float* s_sq  = (float*)(smem + SM_SQ);

    int wsel;
    float* C;
    const float* Asrc = nullptr;
    if (mode == 0) {
        wsel = blockIdx.y;
        Asrc = (wsel == 0) ? fea_last : fea_i;
        C = (wsel == 0) ? g_Q : (wsel == 1 ? g_K : g_V);
    } else {
        wsel = 3;
        C = g_w2;
    }

    if (mode == 1) {
        if (t < 128) {   // compute BN1 affine redundantly per block (replaces k_finalize)
            float mean = g_stat[t] * invc;
            float var  = g_stat[128 + t] * invc - mean * mean;
            float sc = g1[t] * rsqrtf(var + EPS);
            s_aff[t] = sc;
            s_aff[128 + t] = b1[t] - mean * sc;
            s_sum[t] = 0.f;
            s_sq[t]  = 0.f;
        }
        __syncthreads();
    }

    float acc[2][8][4];
#pragma unroll
    for (int mf = 0; mf < 2; mf++)
#pragma unroll
        for (int nf = 0; nf < 8; nf++)
#pragma unroll
            for (int e = 0; e < 4; e++) acc[mf][nf][e] = 0.f;

    int pr = t >> 1;             // prep row
    int half = t & 1;
    int pch = half * 32;         // prep col chunk (local)
    int pn = -1, pj = -1;
    if (mode == 1) {
        int nk = row0 + pr;
        pn = nk >> 4;
        pj = g_idx[nk];
    }

    const __nv_bfloat16* Wsh = g_Wbh + wsel * CIN * CIN;
    const __nv_bfloat16* Wsl = g_Wbl + wsel * CIN * CIN;

#pragma unroll 1
    for (int pass = 0; pass < 2; pass++) {
        int kk0 = pass * 64;
        // ---- B slice via cp.async from presplit gmem (overlaps A prep below)
        {
            const __nv_bfloat16* sh = Wsh + pr * 128 + kk0 + pch;
            const __nv_bfloat16* sl = Wsl + pr * 128 + kk0 + pch;
            uint32_t dh = smem_u32(Bh + (pr * PADK + pch) * 2);
            uint32_t dl = smem_u32(Bl + (pr * PADK + pch) * 2);
#pragma unroll
            for (int c = 0; c < 4; c++) {
                cp16(dh + c * 16, sh + c * 8);
                cp16(dl + c * 16, sl + c * 8);
            }
            CP_COMMIT();
        }
        // ---- A prep (fp32 load/gather + convert + STS)
        {
            if (mode == 0) {
                const float4* Ar = (const float4*)(Asrc + (size_t)(row0 + pr) * 128 + kk0 + pch);
#pragma unroll
                for (int v = 0; v < 8; v++)
                    store_split4(Ah, Al, pr, pch + 4 * v, Ar[v]);
            } else {
                const float4* Qr = (const float4*)(g_Q + (size_t)pn * 128 + kk0 + pch);
                const float4* Kr = (const float4*)(g_K + (size_t)pj * 128 + kk0 + pch);
#pragma unroll
                for (int v = 0; v < 8; v++) {
                    float4 a = Qr[v];
                    float4 b = Kr[v];
                    int cg = kk0 + pch + 4 * v;
                    float x0 = fmaf(a.x - b.x, s_aff[cg + 0], s_aff[128 + cg + 0]);
                    float x1 = fmaf(a.y - b.y, s_aff[cg + 1], s_aff[128 + cg + 1]);
                    float x2 = fmaf(a.z - b.z, s_aff[cg + 2], s_aff[128 + cg + 2]);
                    float x3 = fmaf(a.w - b.w, s_aff[cg + 3], s_aff[128 + cg + 3]);
                    x0 = x0 >= 0.f ? x0 : SLOPE * x0;
                    x1 = x1 >= 0.f ? x1 : SLOPE * x1;
                    x2 = x2 >= 0.f ? x2 : SLOPE * x2;
                    x3 = x3 >= 0.f ? x3 : SLOPE * x3;
                    store_split4(Ah, Al, pr, pch + 4 * v, make_float4(x0, x1, x2, x3));
                }
            }
        }
        CP_WAIT0();
        __syncthreads();

        // ---- 4 K-steps of 16
#pragma unroll
        for (int s = 0; s < 4; s++) {
            int kc = s * 16 + 2 * c4;
            uint32_t ah[2][4], al[2][4], bh[8][2], bl[8][2];
#pragma unroll
            for (int mf = 0; mf < 2; mf++) {
                int r = wm * 32 + mf * 16 + g;
                ah[mf][0] = LDS32(Ah, r,     kc);
                ah[mf][1] = LDS32(Ah, r + 8, kc);
                ah[mf][2] = LDS32(Ah, r,     kc + 8);
                ah[mf][3] = LDS32(Ah, r + 8, kc + 8);
                al[mf][0] = LDS32(Al, r,     kc);
                al[mf][1] = LDS32(Al, r + 8, kc);
                al[mf][2] = LDS32(Al, r,     kc + 8);
                al[mf][3] = LDS32(Al, r + 8, kc + 8);
            }
#pragma unroll
            for (int nf = 0; nf < 8; nf++) {
                int n = wn * 64 + nf * 8 + g;
                bh[nf][0] = LDS32(Bh, n, kc);
                bh[nf][1] = LDS32(Bh, n, kc + 8);
                bl[nf][0] = LDS32(Bl, n, kc);
                bl[nf][1] = LDS32(Bl, n, kc + 8);
            }
#pragma unroll
            for (int mf = 0; mf < 2; mf++)
#pragma unroll
                for (int nf = 0; nf < 8; nf++) {
                    mma16816(acc[mf][nf], ah[mf], bh[nf]);
                    mma16816(acc[mf][nf], al[mf], bh[nf]);
                    mma16816(acc[mf][nf], ah[mf], bl[nf]);
                }
        }
        __syncthreads();
    }

    // ---- epilogue
#pragma unroll
    for (int mf = 0; mf < 2; mf++)
#pragma unroll
        for (int nf = 0; nf < 8; nf++) {
            int row = row0 + wm * 32 + mf * 16 + g;
            int col = wn * 64 + nf * 8 + 2 * c4;
            *(float2*)(C + (size_t)row * 128 + col) =
                make_float2(acc[mf][nf][0], acc[mf][nf][1]);
            *(float2*)(C + (size_t)(row + 8) * 128 + col) =
                make_float2(acc[mf][nf][2], acc[mf][nf][3]);
        }

    if (mode == 1) {
#pragma unroll
        for (int nf = 0; nf < 8; nf++) {
            int col = wn * 64 + nf * 8 + 2 * c4;
            float v00 = acc[0][nf][0], v02 = acc[0][nf][2];
            float v10 = acc[1][nf][0], v12 = acc[1][nf][2];
            atomicAdd(&s_sum[col], v00 + v02 + v10 + v12);
            atomicAdd(&s_sq[col], v00 * v00 + v02 * v02 + v10 * v10 + v12 * v12);
            float v01 = acc[0][nf][1], v03 = acc[0][nf][3];
            float v11 = acc[1][nf][1], v13 = acc[1][nf][3];
            atomicAdd(&s_sum[col + 1], v01 + v03 + v11 + v13);
            atomicAdd(&s_sq[col + 1], v01 * v01 + v03 * v03 + v11 * v11 + v13 * v13);
        }
        __syncthreads();
        if (t < 128) {
            atomicAdd(&g_stat[256 + t], s_sum[t]);
            atomicAdd(&g_stat[384 + t], s_sq[t]);
        }
    }
}

// ---------------- k_stats: BN1 stats via S/T decomposition ----------------
// sum (Q-K) = 16Q - S ; sum (Q-K)^2 = 16Q^2 - 2QS + T, S=sum K, T=sum K^2
__global__ void __launch_bounds__(256) k_stats(int N) {
    int t = threadIdx.x;
    int c = t & 127, h = t >> 7;
    int n0 = blockIdx.x * 64;
    float s1 = 0.f, q1 = 0.f;
    for (int i = h; i < 64; i += 2) {
        int n = n0 + i;
        float Q = g_Q[(size_t)n * 128 + c];
        float S = 0.f, T = 0.f;
#pragma unroll
        for (int k = 0; k < KNN; k++) {
            int j = g_idx[n * KNN + k];          // warp-uniform -> broadcast
            float v = g_K[(size_t)j * 128 + c];  // coalesced
            S += v;
            T = fmaf(v, v, T);
        }
        s1 += 16.f * Q - S;
        q1 += fmaf(16.f * Q, Q, fmaf(-2.f * Q, S, T));
    }
    __shared__ float sh[256];
    sh[t] = s1; __syncthreads();
    if (h == 0) atomicAdd(&g_stat[c], sh[c] + sh[128 + c]);
    __syncthreads();
    sh[t] = q1; __syncthreads();
    if (h == 0) atomicAdd(&g_stat[128 + c], sh[c] + sh[128 + c]);
}

// ---------------- k_out: aff2 + leaky + softmax + weighted V sum ----------------
__global__ void k_out(const float* __restrict__ bv,
                      const float* __restrict__ g2, const float* __restrict__ b2,
                      float invc, float* __restrict__ out, int N) {
    int n = blockIdx.x;
    int c = threadIdx.x;
    __shared__ int sidx[KNN];
    if (c < KNN) sidx[c] = g_idx[n * KNN + c];
    __syncthreads();

    float mean2 = g_stat[256 + c] * invc;
    float var2  = g_stat[384 + c] * invc - mean2 * mean2;
    float sc2 = g2[c] * rsqrtf(var2 + EPS);
    float sh2 = b2[c] - mean2 * sc2;

    float tv[KNN];
    float m = -1e30f;
#pragma unroll
    for (int k = 0; k < KNN; k++) {
        float x = g_w2[(size_t)(n * KNN + k) * 128 + c];
        x = fmaf(x, sc2, sh2);
        x = x >= 0.f ? x : SLOPE * x;
        tv[k] = x;
        m = fmaxf(m, x);
    }
    float s = 0.f;
#pragma unroll
    for (int k = 0; k < KNN; k++) { float e = __expf(tv[k] - m); tv[k] = e; s += e; }
    float inv = 1.f / s;
    float b = bv[c];
    float acc = 0.f;
#pragma unroll
    for (int k = 0; k < KNN; k++) {
        float v = g_V[(size_t)sidx[k] * 128 + c] + b;
        acc = fmaf(tv[k] * inv, v, acc);
    }
    out[(size_t)n * 128 + c] = acc;
}

// ---------------- launch ----------------
extern "C" void kernel_launch(void* const* d_in, const int* in_sizes, int n_in,
                              void* d_out, int out_size) {
    const float* fea_i    = (const float*)d_in[0];
    const float* fea_last = (const float*)d_in[1];
    const float* xyz_i    = (const float*)d_in[2];
    const float* xyz_last = (const float*)d_in[3];
    const float* Wq = (const float*)d_in[5];
    const float* Wk = (const float*)d_in[7];
    const float* Wv = (const float*)d_in[9];
    const float* bv = (const float*)d_in[10];
    const float* g1 = (const float*)d_in[11];
    const float* b1 = (const float*)d_in[12];
    const float* Wl = (const float*)d_in[13];
    const float* g2 = (const float*)d_in[15];
    const float* b2 = (const float*)d_in[16];

    int N = in_sizes[0] / CIN;
    float invc = 1.0f / (float)(N * KNN);

    cudaFuncSetAttribute(k_mma_gemm, cudaFuncAttributeMaxDynamicSharedMemorySize, SMEM_TOTAL);

    k_build<<<1, 1024>>>(xyz_i, Wq, Wk, Wv, Wl, N);                 // idx 0

    dim3 gq(N / 128, 3);
    k_mma_gemm<<<gq, 256, SMEM_TOTAL>>>(0, fea_i, fea_last, g1, b1, invc);  // idx 1

    k_knn_warp<<<(N + 7) / 8, 256>>>(xyz_last, N);                  // idx 2

    k_stats<<<N / 64, 256>>>(N);                                    // idx 3 (profiled)

    k_mma_gemm<<<N * KNN / 128, 256, SMEM_TOTAL>>>(1, fea_i, fea_last, g1, b1, invc); // idx 4

    k_out<<<N, 128>>>(bv, g2, b2, invc, (float*)d_out, N);          // idx 5
}

// round 8
// speedup vs baseline: 1.9651x; 1.1302x over previous
#include <cuda_runtime.h>
#include <cuda_bf16.h>
#include <cstdint>

#define CIN 128
#define KNN 16
#define NMAX 8192
#define EPS 1e-5f
#define SLOPE 0.01f
#define GRID 8
#define NCELL (GRID * GRID * GRID)
#define CELLH (1.0f / GRID)
#define PADK 72   // bf16 stride per smem row; frag-load banks 4*g + c4 -> conflict-free

// ---------------- scratch (static device memory; no allocations) ----------------
__device__ int   g_idx[NMAX * KNN];
__device__ int   g_cid[NMAX];
__device__ int   g_cellstart[NCELL + 1];
__device__ __align__(16) float4 g_cellpts[NMAX];   // (x,y,z, idx-as-float-bits)
__device__ __align__(16) float g_Q[NMAX * CIN];
__device__ __align__(16) float g_K[NMAX * CIN];
__device__ __align__(16) float g_V[NMAX * CIN];
__device__ __align__(16) float g_w2[(size_t)NMAX * KNN * CIN];
__device__ float g_stat[4 * CIN];   // [0:128)=sum1 [128:256)=sq1 [256:384)=sum2 [384:512)=sq2
__device__ __align__(16) __nv_bfloat16 g_Wbh[4 * CIN * CIN];  // weight splits hi (Wq,Wk,Wv,Wl)
__device__ __align__(16) __nv_bfloat16 g_Wbl[4 * CIN * CIN];  // weight splits lo

__device__ __forceinline__ int cell1(float x) {
    int c = (int)(x * (float)GRID);
    return c < 0 ? 0 : (c > GRID - 1 ? GRID - 1 : c);
}

__device__ __forceinline__ uint32_t smem_u32(const void* p) {
    uint32_t a;
    asm("{ .reg .u64 t; cvta.to.shared.u64 t, %1; cvt.u32.u64 %0, t; }" : "=r"(a) : "l"(p));
    return a;
}
__device__ __forceinline__ void cp16(uint32_t dst, const void* src) {
    asm volatile("cp.async.cg.shared.global [%0], [%1], 16;" :: "r"(dst), "l"(src));
}
#define CP_COMMIT() asm volatile("cp.async.commit_group;")
#define CP_WAIT0()  asm volatile("cp.async.wait_group 0;" ::: "memory")

// fp32 -> (bf16 hi, bf16 lo) pair pack
__device__ __forceinline__ void split_pair(float x0, float x1, uint32_t& hp, uint32_t& lp) {
    __nv_bfloat16 h0 = __float2bfloat16(x0);
    __nv_bfloat16 h1 = __float2bfloat16(x1);
    __nv_bfloat16 l0 = __float2bfloat16(x0 - __bfloat162float(h0));
    __nv_bfloat16 l1 = __float2bfloat16(x1 - __bfloat162float(h1));
    hp = ((uint32_t)__bfloat16_as_ushort(h1) << 16) | __bfloat16_as_ushort(h0);
    lp = ((uint32_t)__bfloat16_as_ushort(l1) << 16) | __bfloat16_as_ushort(l0);
}

__device__ __forceinline__ void store_split4(char* hi, char* lo, int r, int c, float4 a) {
    uint32_t h0, l0, h1, l1;
    split_pair(a.x, a.y, h0, l0);
    split_pair(a.z, a.w, h1, l1);
    int off = (r * PADK + c) * 2;
    *(uint32_t*)(hi + off)     = h0;
    *(uint32_t*)(lo + off)     = l0;
    *(uint32_t*)(hi + off + 4) = h1;
    *(uint32_t*)(lo + off + 4) = l1;
}

__device__ __forceinline__ void mma16816(float* d, const uint32_t* a, const uint32_t* b) {
    asm volatile(
        "mma.sync.aligned.m16n8k16.row.col.f32.bf16.bf16.f32 "
        "{%0,%1,%2,%3}, {%4,%5,%6,%7}, {%8,%9}, {%0,%1,%2,%3};"
        : "+f"(d[0]), "+f"(d[1]), "+f"(d[2]), "+f"(d[3])
        : "r"(a[0]), "r"(a[1]), "r"(a[2]), "r"(a[3]), "r"(b[0]), "r"(b[1]));
}

// ---------------- k_build: block 0 = grid build + stat zero, blocks 1..8 = weight presplit --
__global__ void __launch_bounds__(1024) k_build(
    const float* __restrict__ xyz_i,
    const float* __restrict__ Wq, const float* __restrict__ Wk,
    const float* __restrict__ Wv, const float* __restrict__ Wl, int N)
{
    int t = threadIdx.x;
    int b = blockIdx.x;

    if (b > 0) {
        // weight presplit: 4 matrices x 8192 float2-pairs; blocks 1..8, 4096 pairs each
        uint32_t* oh = (uint32_t*)g_Wbh;
        uint32_t* ol = (uint32_t*)g_Wbl;
        int e0 = (b - 1) * 4096;
#pragma unroll
        for (int v = 0; v < 4; v++) {
            int e = e0 + v * 1024 + t;
            int m = e >> 13;
            int off = (e & 8191) * 2;
            const float* W = (m == 0) ? Wq : (m == 1 ? Wk : (m == 2 ? Wv : Wl));
            float2 x = *(const float2*)(W + off);
            uint32_t hp, lp;
            split_pair(x.x, x.y, hp, lp);
            oh[e] = hp;
            ol[e] = lp;
        }
        return;
    }

    __shared__ int scnt[NCELL];
    __shared__ int spre[NCELL];
    __shared__ int scur[NCELL];

    if (t < NCELL) scnt[t] = 0;
    if (t < 4 * CIN) g_stat[t] = 0.f;
    __syncthreads();

    for (int i = t; i < N; i += 1024) {
        float x = xyz_i[i * 3 + 0], y = xyz_i[i * 3 + 1], z = xyz_i[i * 3 + 2];
        int cid = (cell1(z) * GRID + cell1(y)) * GRID + cell1(x);
        g_cid[i] = cid;
        atomicAdd(&scnt[cid], 1);
    }
    __syncthreads();

    if (t < NCELL) spre[t] = scnt[t];
    __syncthreads();
    for (int o = 1; o < NCELL; o <<= 1) {
        int v = (t >= o && t < NCELL) ? spre[t - o] : 0;
        __syncthreads();
        if (t < NCELL) spre[t] += v;
        __syncthreads();
    }
    if (t < NCELL) {
        int excl = spre[t] - scnt[t];
        g_cellstart[t] = excl;
        scur[t] = excl;
    }
    if (t == NCELL - 1) g_cellstart[NCELL] = spre[NCELL - 1];
    __syncthreads();

    for (int i = t; i < N; i += 1024) {
        float x = xyz_i[i * 3 + 0], y = xyz_i[i * 3 + 1], z = xyz_i[i * 3 + 2];
        int slot = atomicAdd(&scur[g_cid[i]], 1);
        g_cellpts[slot] = make_float4(x, y, z, __int_as_float(i));
    }
}

// ---------------- serial fallback knn (exact, shell expansion) ----------------
__device__ void knn_serial(int q, float qx, float qy, float qz, int cx, int cy, int cz) {
    float bd[KNN];
    int   bi[KNN];
#pragma unroll
    for (int s = 0; s < KNN; s++) { bd[s] = 1e30f; bi[s] = -1; }
    float curmax = 1e30f;
    int maxslot = 0;
    for (int R = 0; R < GRID; R++) {
        int zlo = cz - R < 0 ? 0 : cz - R, zhi = cz + R > GRID - 1 ? GRID - 1 : cz + R;
        int ylo = cy - R < 0 ? 0 : cy - R, yhi = cy + R > GRID - 1 ? GRID - 1 : cy + R;
        int xlo = cx - R < 0 ? 0 : cx - R, xhi = cx + R > GRID - 1 ? GRID - 1 : cx + R;
        for (int zz = zlo; zz <= zhi; zz++) {
            int adz = zz - cz; adz = adz < 0 ? -adz : adz;
            for (int yy = ylo; yy <= yhi; yy++) {
                int ady = yy - cy; ady = ady < 0 ? -ady : ady;
                int rowmax = adz > ady ? adz : ady;
                for (int xx = xlo; xx <= xhi; xx++) {
                    int adx = xx - cx; adx = adx < 0 ? -adx : adx;
                    int cheb = rowmax > adx ? rowmax : adx;
                    if (cheb != R) continue;
                    int cellid = (zz * GRID + yy) * GRID + xx;
                    int s0 = g_cellstart[cellid];
                    int s1 = g_cellstart[cellid + 1];
                    for (int s = s0; s < s1; s++) {
                        float4 p = g_cellpts[s];
                        float dx = qx - p.x, dy = qy - p.y, dz = qz - p.z;
                        float d2 = fmaf(dx, dx, fmaf(dy, dy, dz * dz));
                        if (d2 < curmax) {
                            int j = __float_as_int(p.w);
#pragma unroll
                            for (int u = 0; u < KNN; u++)
                                if (u == maxslot) { bd[u] = d2; bi[u] = j; }
                            curmax = -1.f;
#pragma unroll
                            for (int u = 0; u < KNN; u++)
                                if (bd[u] > curmax) { curmax = bd[u]; maxslot = u; }
                        }
                    }
                }
            }
        }
        float reach = (float)R * CELLH;
        if (curmax <= reach * reach) break;
    }
#pragma unroll
    for (int s = 0; s < KNN; s++) g_idx[q * KNN + s] = bi[s];
}

// ---------------- warp-per-query knn + fused BN1 stats ----------------
__global__ void __launch_bounds__(256) k_knn_warp(const float* __restrict__ xyz_last, int N) {
    __shared__ int s_pre[8][12];
    __shared__ int s_s0[8][12];
    __shared__ float s_sum[128], s_sq[128];
    int w = threadIdx.x >> 5;
    int lid = threadIdx.x & 31;
    int q = (blockIdx.x * 256 + threadIdx.x) >> 5;

    if (threadIdx.x < 128) { s_sum[threadIdx.x] = 0.f; s_sq[threadIdx.x] = 0.f; }
    __syncthreads();

    bool valid = (q < N);
    if (valid) {
        float qx = xyz_last[q * 3 + 0];
        float qy = xyz_last[q * 3 + 1];
        float qz = xyz_last[q * 3 + 2];
        int cx = cell1(qx), cy = cell1(qy), cz = cell1(qz);

        int zlo = cz - 1 < 0 ? 0 : cz - 1, zhi = cz + 1 > GRID - 1 ? GRID - 1 : cz + 1;
        int ylo = cy - 1 < 0 ? 0 : cy - 1, yhi = cy + 1 > GRID - 1 ? GRID - 1 : cy + 1;
        int xlo = cx - 1 < 0 ? 0 : cx - 1, xhi = cx + 1 > GRID - 1 ? GRID - 1 : cx + 1;
        int ny = yhi - ylo + 1;
        int nrows = (zhi - zlo + 1) * ny;   // <= 9

        int s0 = 0, len = 0;
        if (lid < nrows) {
            int zz = zlo + lid / ny;
            int yy = ylo + lid % ny;
            int cbase = (zz * GRID + yy) * GRID;
            s0 = g_cellstart[cbase + xlo];
            len = g_cellstart[cbase + xhi + 1] - s0;
        }
        int pre = len;
#pragma unroll
        for (int o = 1; o < 32; o <<= 1) {
            int v = __shfl_up_sync(0xFFFFFFFFu, pre, o);
            if (lid >= o) pre += v;
        }
        int T = __shfl_sync(0xFFFFFFFFu, pre, 31);
        int myStart = pre - len;

        if (lid < 12) { s_pre[w][lid] = 0x7FFFFFFF; s_s0[w][lid] = 0; }
        __syncwarp();
        if (lid <= nrows && lid < 10) s_pre[w][lid] = myStart;
        if (lid < nrows) s_s0[w][lid] = s0;
        __syncwarp();

        float bd[KNN];
        int   bi[KNN];
#pragma unroll
        for (int s = 0; s < KNN; s++) { bd[s] = 1e30f; bi[s] = -1; }
        float curmax = 1e30f;
        int maxslot = 0;

        int niter = (T + 31) >> 5;
        for (int it = 0; it < niter; it++) {
            int c = it * 32 + lid;
            if (c < T) {
                int j = 0;
#pragma unroll
                for (int i = 1; i <= 9; i++) j += (c >= s_pre[w][i]) ? 1 : 0;
                int slot = s_s0[w][j] + (c - s_pre[w][j]);
                float4 p = g_cellpts[slot];
                float dx = qx - p.x, dy = qy - p.y, dz = qz - p.z;
                float d2 = fmaf(dx, dx, fmaf(dy, dy, dz * dz));
                if (d2 < curmax) {
                    int ji = __float_as_int(p.w);
#pragma unroll
                    for (int u = 0; u < KNN; u++)
                        if (u == maxslot) { bd[u] = d2; bi[u] = ji; }
                    curmax = -1.f;
#pragma unroll
                    for (int u = 0; u < KNN; u++)
                        if (bd[u] > curmax) { curmax = bd[u]; maxslot = u; }
                }
            }
        }

        // 16-round warp argmin extraction
        float lmin = 1e30f;
        int lslot = 0;
#pragma unroll
        for (int s = 0; s < KNN; s++)
            if (bd[s] < lmin) { lmin = bd[s]; lslot = s; }

        float d16 = 0.f;
        int myres = -1;
        for (int r = 0; r < KNN; r++) {
            float v = lmin;
            int wl = lid;
#pragma unroll
            for (int o = 16; o; o >>= 1) {
                float ov = __shfl_xor_sync(0xFFFFFFFFu, v, o);
                int owl = __shfl_xor_sync(0xFFFFFFFFu, wl, o);
                if (ov < v || (ov == v && owl < wl)) { v = ov; wl = owl; }
            }
            int myidx = -1;
#pragma unroll
            for (int s = 0; s < KNN; s++)
                if (s == lslot) myidx = bi[s];
            int wi = __shfl_sync(0xFFFFFFFFu, myidx, wl);
            d16 = v;
            if (lid == r) myres = wi;
            if (lid == wl) {
#pragma unroll
                for (int s = 0; s < KNN; s++)
                    if (s == lslot) bd[s] = 1e30f;
                lmin = 1e30f; lslot = 0;
#pragma unroll
                for (int s = 0; s < KNN; s++)
                    if (bd[s] < lmin) { lmin = bd[s]; lslot = s; }
            }
        }

        if (d16 <= CELLH * CELLH) {
            if (lid < KNN) g_idx[q * KNN + lid] = myres;
        } else {
            if (lid == 0) knn_serial(q, qx, qy, qz, cx, cy, cz);
        }
        __syncwarp();

        // ---- fused BN1 stats: lane owns 4 channels cb..cb+3 of query q
        {
            int cb = lid * 4;
            float4 Qv = *(const float4*)(g_Q + (size_t)q * 128 + cb);
            float S0 = 0.f, S1 = 0.f, S2 = 0.f, S3 = 0.f;
            float T0 = 0.f, T1 = 0.f, T2 = 0.f, T3 = 0.f;
#pragma unroll
            for (int k = 0; k < KNN; k++) {
                int j = g_idx[q * KNN + k];          // warp-uniform broadcast
                float4 kv = *(const float4*)(g_K + (size_t)j * 128 + cb);
                S0 += kv.x; T0 = fmaf(kv.x, kv.x, T0);
                S1 += kv.y; T1 = fmaf(kv.y, kv.y, T1);
                S2 += kv.z; T2 = fmaf(kv.z, kv.z, T2);
                S3 += kv.w; T3 = fmaf(kv.w, kv.w, T3);
            }
            atomicAdd(&s_sum[cb + 0], 16.f * Qv.x - S0);
            atomicAdd(&s_sum[cb + 1], 16.f * Qv.y - S1);
            atomicAdd(&s_sum[cb + 2], 16.f * Qv.z - S2);
            atomicAdd(&s_sum[cb + 3], 16.f * Qv.w - S3);
            atomicAdd(&s_sq[cb + 0], fmaf(16.f * Qv.x, Qv.x, fmaf(-2.f * Qv.x, S0, T0)));
            atomicAdd(&s_sq[cb + 1], fmaf(16.f * Qv.y, Qv.y, fmaf(-2.f * Qv.y, S1, T1)));
            atomicAdd(&s_sq[cb + 2], fmaf(16.f * Qv.z, Qv.z, fmaf(-2.f * Qv.z, S2, T2)));
            atomicAdd(&s_sq[cb + 3], fmaf(16.f * Qv.w, Qv.w, fmaf(-2.f * Qv.w, S3, T3)));
        }
    }
    __syncthreads();
    if (threadIdx.x < 128) {
        atomicAdd(&g_stat[threadIdx.x], s_sum[threadIdx.x]);
        atomicAdd(&g_stat[128 + threadIdx.x], s_sq[threadIdx.x]);
    }
}

// ---------------- mma.sync GEMM, K-tiled (BK=64, 2 passes), B via cp.async presplit --
#define TILEB (128 * PADK * 2)            // 18432
#define SM_AHI 0
#define SM_ALO TILEB
#define SM_BHI (2 * TILEB)
#define SM_BLO (3 * TILEB)
#define SM_AFF (4 * TILEB)                // 256 floats
#define SM_SUM (SM_AFF + 1024)            // 128 floats
#define SM_SQ  (SM_SUM + 512)             // 128 floats
#define SMEM_TOTAL (SM_SQ + 512)          // ~74 KB -> 2 blocks/SM (reg-limited)

#define LDS32(base, r, col) (*(const uint32_t*)((base) + ((r) * PADK + (col)) * 2))

__global__ void __launch_bounds__(256, 2) k_mma_gemm(
    int mode,
    const float* __restrict__ fea_i, const float* __restrict__ fea_last,
    const float* __restrict__ g1, const float* __restrict__ b1, float invc)
{
    extern __shared__ char smem[];
    int t = threadIdx.x;
    int lane = t & 31, wid = t >> 5;
    int g = lane >> 2, c4 = lane & 3;
    int wm = wid & 3, wn = wid >> 2;
    int row0 = blockIdx.x * 128;

    char* Ah = smem + SM_AHI;
    char* Al = smem + SM_ALO;
    char* Bh = smem + SM_BHI;
    char* Bl = smem + SM_BLO;
    float* s_aff = (float*)(smem + SM_AFF);
    float* s_sum = (float*)(smem + SM_SUM);
    float* s_sq  = (float*)(smem + SM_SQ);

    int wsel;
    float* C;
    const float* Asrc = nullptr;
    if (mode == 0) {
        wsel = blockIdx.y;
        Asrc = (wsel == 0) ? fea_last : fea_i;
        C = (wsel == 0) ? g_Q : (wsel == 1 ? g_K : g_V);
    } else {
        wsel = 3;
        C = g_w2;
    }

    if (mode == 1) {
        if (t < 128) {   // BN1 affine computed per block (no separate finalize kernel)
            float mean = g_stat[t] * invc;
            float var  = g_stat[128 + t] * invc - mean * mean;
            float sc = g1[t] * rsqrtf(var + EPS);
            s_aff[t] = sc;
            s_aff[128 + t] = b1[t] - mean * sc;
            s_sum[t] = 0.f;
            s_sq[t]  = 0.f;
        }
        __syncthreads();
    }

    float acc[2][8][4];
#pragma unroll
    for (int mf = 0; mf < 2; mf++)
#pragma unroll
        for (int nf = 0; nf < 8; nf++)
#pragma unroll
            for (int e = 0; e < 4; e++) acc[mf][nf][e] = 0.f;

    int pr = t >> 1;             // prep row
    int half = t & 1;
    int pch = half * 32;         // prep col chunk (local)
    int pn = -1, pj = -1;
    if (mode == 1) {
        int nk = row0 + pr;
        pn = nk >> 4;
        pj = g_idx[nk];
    }

    const __nv_bfloat16* Wsh = g_Wbh + wsel * CIN * CIN;
    const __nv_bfloat16* Wsl = g_Wbl + wsel * CIN * CIN;

#pragma unroll 1
    for (int pass = 0; pass < 2; pass++) {
        int kk0 = pass * 64;
        // B slice via cp.async (overlaps A prep)
        {
            const __nv_bfloat16* sh = Wsh + pr * 128 + kk0 + pch;
            const __nv_bfloat16* sl = Wsl + pr * 128 + kk0 + pch;
            uint32_t dh = smem_u32(Bh + (pr * PADK + pch) * 2);
            uint32_t dl = smem_u32(Bl + (pr * PADK + pch) * 2);
#pragma unroll
            for (int c = 0; c < 4; c++) {
                cp16(dh + c * 16, sh + c * 8);
                cp16(dl + c * 16, sl + c * 8);
            }
            CP_COMMIT();
        }
        // A prep
        {
            if (mode == 0) {
                const float4* Ar = (const float4*)(Asrc + (size_t)(row0 + pr) * 128 + kk0 + pch);
#pragma unroll
                for (int v = 0; v < 8; v++)
                    store_split4(Ah, Al, pr, pch + 4 * v, Ar[v]);
            } else {
                const float4* Qr = (const float4*)(g_Q + (size_t)pn * 128 + kk0 + pch);
                const float4* Kr = (const float4*)(g_K + (size_t)pj * 128 + kk0 + pch);
#pragma unroll
                for (int v = 0; v < 8; v++) {
                    float4 a = Qr[v];
                    float4 b = Kr[v];
                    int cg = kk0 + pch + 4 * v;
                    float x0 = fmaf(a.x - b.x, s_aff[cg + 0], s_aff[128 + cg + 0]);
                    float x1 = fmaf(a.y - b.y, s_aff[cg + 1], s_aff[128 + cg + 1]);
                    float x2 = fmaf(a.z - b.z, s_aff[cg + 2], s_aff[128 + cg + 2]);
                    float x3 = fmaf(a.w - b.w, s_aff[cg + 3], s_aff[128 + cg + 3]);
                    x0 = x0 >= 0.f ? x0 : SLOPE * x0;
                    x1 = x1 >= 0.f ? x1 : SLOPE * x1;
                    x2 = x2 >= 0.f ? x2 : SLOPE * x2;
                    x3 = x3 >= 0.f ? x3 : SLOPE * x3;
                    store_split4(Ah, Al, pr, pch + 4 * v, make_float4(x0, x1, x2, x3));
                }
            }
        }
        CP_WAIT0();
        __syncthreads();

        // 4 K-steps of 16
#pragma unroll
        for (int s = 0; s < 4; s++) {
            int kc = s * 16 + 2 * c4;
            uint32_t ah[2][4], al[2][4], bh[8][2], bl[8][2];
#pragma unroll
            for (int mf = 0; mf < 2; mf++) {
                int r = wm * 32 + mf * 16 + g;
                ah[mf][0] = LDS32(Ah, r,     kc);
                ah[mf][1] = LDS32(Ah, r + 8, kc);
                ah[mf][2] = LDS32(Ah, r,     kc + 8);
                ah[mf][3] = LDS32(Ah, r + 8, kc + 8);
                al[mf][0] = LDS32(Al, r,     kc);
                al[mf][1] = LDS32(Al, r + 8, kc);
                al[mf][2] = LDS32(Al, r,     kc + 8);
                al[mf][3] = LDS32(Al, r + 8, kc + 8);
            }
#pragma unroll
            for (int nf = 0; nf < 8; nf++) {
                int n = wn * 64 + nf * 8 + g;
                bh[nf][0] = LDS32(Bh, n, kc);
                bh[nf][1] = LDS32(Bh, n, kc + 8);
                bl[nf][0] = LDS32(Bl, n, kc);
                bl[nf][1] = LDS32(Bl, n, kc + 8);
            }
#pragma unroll
            for (int mf = 0; mf < 2; mf++)
#pragma unroll
                for (int nf = 0; nf < 8; nf++) {
                    mma16816(acc[mf][nf], ah[mf], bh[nf]);
                    mma16816(acc[mf][nf], al[mf], bh[nf]);
                    mma16816(acc[mf][nf], ah[mf], bl[nf]);
                }
        }
        __syncthreads();
    }

    // epilogue
#pragma unroll
    for (int mf = 0; mf < 2; mf++)
#pragma unroll
        for (int nf = 0; nf < 8; nf++) {
            int row = row0 + wm * 32 + mf * 16 + g;
            int col = wn * 64 + nf * 8 + 2 * c4;
            *(float2*)(C + (size_t)row * 128 + col) =
                make_float2(acc[mf][nf][0], acc[mf][nf][1]);
            *(float2*)(C + (size_t)(row + 8) * 128 + col) =
                make_float2(acc[mf][nf][2], acc[mf][nf][3]);
        }

    if (mode == 1) {
#pragma unroll
        for (int nf = 0; nf < 8; nf++) {
            int col = wn * 64 + nf * 8 + 2 * c4;
            float v00 = acc[0][nf][0], v02 = acc[0][nf][2];
            float v10 = acc[1][nf][0], v12 = acc[1][nf][2];
            atomicAdd(&s_sum[col], v00 + v02 + v10 + v12);
            atomicAdd(&s_sq[col], v00 * v00 + v02 * v02 + v10 * v10 + v12 * v12);
            float v01 = acc[0][nf][1], v03 = acc[0][nf][3];
            float v11 = acc[1][nf][1], v13 = acc[1][nf][3];
            atomicAdd(&s_sum[col + 1], v01 + v03 + v11 + v13);
            atomicAdd(&s_sq[col + 1], v01 * v01 + v03 * v03 + v11 * v11 + v13 * v13);
        }
        __syncthreads();
        if (t < 128) {
            atomicAdd(&g_stat[256 + t], s_sum[t]);
            atomicAdd(&g_stat[384 + t], s_sq[t]);
        }
    }
}

// ---------------- k_out: aff2 + leaky + softmax + weighted V sum ----------------
__global__ void k_out(const float* __restrict__ bv,
                      const float* __restrict__ g2, const float* __restrict__ b2,
                      float invc, float* __restrict__ out, int N) {
    int n = blockIdx.x;
    int c = threadIdx.x;
    __shared__ int sidx[KNN];
    if (c < KNN) sidx[c] = g_idx[n * KNN + c];
    __syncthreads();

    float mean2 = g_stat[256 + c] * invc;
    float var2  = g_stat[384 + c] * invc - mean2 * mean2;
    float sc2 = g2[c] * rsqrtf(var2 + EPS);
    float sh2 = b2[c] - mean2 * sc2;

    float tv[KNN];
    float m = -1e30f;
#pragma unroll
    for (int k = 0; k < KNN; k++) {
        float x = g_w2[(size_t)(n * KNN + k) * 128 + c];
        x = fmaf(x, sc2, sh2);
        x = x >= 0.f ? x : SLOPE * x;
        tv[k] = x;
        m = fmaxf(m, x);
    }
    float s = 0.f;
#pragma unroll
    for (int k = 0; k < KNN; k++) { float e = __expf(tv[k] - m); tv[k] = e; s += e; }
    float inv = 1.f / s;
    float b = bv[c];
    float acc = 0.f;
#pragma unroll
    for (int k = 0; k < KNN; k++) {
        float v = g_V[(size_t)sidx[k] * 128 + c] + b;
        acc = fmaf(tv[k] * inv, v, acc);
    }
    out[(size_t)n * 128 + c] = acc;
}

// ---------------- launch ----------------
extern "C" void kernel_launch(void* const* d_in, const int* in_sizes, int n_in,
                              void* d_out, int out_size) {
    const float* fea_i    = (const float*)d_in[0];
    const float* fea_last = (const float*)d_in[1];
    const float* xyz_i    = (const float*)d_in[2];
    const float* xyz_last = (const float*)d_in[3];
    const float* Wq = (const float*)d_in[5];
    const float* Wk = (const float*)d_in[7];
    const float* Wv = (const float*)d_in[9];
    const float* bv = (const float*)d_in[10];
    const float* g1 = (const float*)d_in[11];
    const float* b1 = (const float*)d_in[12];
    const float* Wl = (const float*)d_in[13];
    const float* g2 = (const float*)d_in[15];
    const float* b2 = (const float*)d_in[16];

    int N = in_sizes[0] / CIN;
    float invc = 1.0f / (float)(N * KNN);

    cudaFuncSetAttribute(k_mma_gemm, cudaFuncAttributeMaxDynamicSharedMemorySize, SMEM_TOTAL);

    k_build<<<9, 1024>>>(xyz_i, Wq, Wk, Wv, Wl, N);                 // idx 0

    dim3 gq(N / 128, 3);
    k_mma_gemm<<<gq, 256, SMEM_TOTAL>>>(0, fea_i, fea_last, g1, b1, invc);  // idx 1

    k_knn_warp<<<(N + 7) / 8, 256>>>(xyz_last, N);                  // idx 2 (knn + BN1 stats)

    k_mma_gemm<<<N * KNN / 128, 256, SMEM_TOTAL>>>(1, fea_i, fea_last, g1, b1, invc); // idx 3 (profiled)

    k_out<<<N, 128>>>(bv, g2, b2, invc, (float*)d_out, N);          // idx 4
}